// round 12
// baseline (speedup 1.0000x reference)
#include <cuda_runtime.h>
#include <cuda_fp16.h>
#include <math.h>
#include <stdint.h>

// Problem constants
#define BB 32
#define CC 64
#define LL 2048
#define DD 50
#define DK 64
#define TL 128
#define NLT (LL/TL)    // 16
#define NMT (LL/128)   // 16

// Scratch (device globals — allocation is forbidden)
// g_Kh/g_Qh: fp16, d interleaved within 16-chunks: pos 4q..4q+3 hold d = 2q,2q+1,2q+8,2q+9.
// g_Kh pre-scaled by log2e/sqrt(sample_len).
__device__ __half g_Kh[BB*LL*DK];
__device__ __half g_Qh[BB*LL*DK];
__device__ float  g_V[BB*LL*CC];          // tanh(xWv+bv), [m][c] fp32
__device__ __half g_Vph[BB*CC*LL];        // V' = V*cinv, [c][m'] perm16 on m
__device__ float  g_part[NLT*BB*LL];      // per-ltile column partials

#define LDQH 80        // halves; 40 words -> phase-conflict-free LDS.64
#define LDVH 144       // halves

__device__ __forceinline__ float read_len(const void* p) {
    int i = *(const int*)p;
    if (i > 0 && i < (1 << 24)) return (float)i;
    return __int_as_float(i);
}
__device__ __forceinline__ uint32_t f2tf32(float x) {
    uint32_t u;
    asm("cvt.rna.tf32.f32 %0, %1;" : "=r"(u) : "f"(x));
    return u;
}
__device__ __forceinline__ uint32_t packh2(float lo, float hi) {
    __half2 h = __floats2half2_rn(lo, hi);
    return *(uint32_t*)&h;
}
__device__ __forceinline__ uint32_t ex2h2(uint32_t v) {
    uint32_t r;
    asm("ex2.approx.f16x2 %0, %1;" : "=r"(r) : "r"(v));
    return r;
}
// D += A(16x8 tf32) * B(8x8 tf32)
__device__ __forceinline__ void mma8(float* d, const uint32_t* a, uint32_t b0, uint32_t b1) {
    asm volatile("mma.sync.aligned.m16n8k8.row.col.f32.tf32.tf32.f32 "
                 "{%0,%1,%2,%3}, {%4,%5,%6,%7}, {%8,%9}, {%0,%1,%2,%3};"
                 : "+f"(d[0]), "+f"(d[1]), "+f"(d[2]), "+f"(d[3])
                 : "r"(a[0]), "r"(a[1]), "r"(a[2]), "r"(a[3]), "r"(b0), "r"(b1));
}
// D += A(16x16 f16) * B(16x8 f16)
__device__ __forceinline__ void mma16(float* d, uint32_t a0, uint32_t a1, uint32_t a2,
                                      uint32_t a3, uint32_t b0, uint32_t b1) {
    asm volatile("mma.sync.aligned.m16n8k16.row.col.f32.f16.f16.f32 "
                 "{%0,%1,%2,%3}, {%4,%5,%6,%7}, {%8,%9}, {%0,%1,%2,%3};"
                 : "+f"(d[0]), "+f"(d[1]), "+f"(d[2]), "+f"(d[3])
                 : "r"(a0), "r"(a1), "r"(a2), "r"(a3), "r"(b0), "r"(b1));
}

// S tile GEMM1: rows (via Ka), cols 16t..16t+15, from Qhs
__device__ __forceinline__ void gemm1_tile(const __half* Qhs, int t,
                                           const uint32_t Ka[4][4], int g, int q,
                                           float* a0, float* a1) {
#pragma unroll
    for (int e = 0; e < 4; e++) { a0[e] = 0.f; a1[e] = 0.f; }
#pragma unroll
    for (int ks = 0; ks < 4; ks++) {
        uint2 q0 = *(const uint2*)&Qhs[(16 * t + g) * LDQH + 16 * ks + 4 * q];
        uint2 q1 = *(const uint2*)&Qhs[(16 * t + 8 + g) * LDQH + 16 * ks + 4 * q];
        mma16(a0, Ka[ks][0], Ka[ks][1], Ka[ks][2], Ka[ks][3], q0.x, q0.y);
        mma16(a1, Ka[ks][0], Ka[ks][1], Ka[ks][2], Ka[ks][3], q1.x, q1.y);
    }
}

// ---------------------------------------------------------------------------
// Kernel 1: projections via tf32 mma8. grid (16, 32), 256 thr (8 warps x 16 l).
// ---------------------------------------------------------------------------
#define KQ_XS   0
#define KQ_WS   (KQ_XS + 64*136)
#define KQ_STG  (KQ_WS + 176*72)
#define KQ_BIA  (KQ_STG + 128*72)
#define KQ_TOT  (KQ_BIA + 176)
#define LDX 136
#define LDW 72

__global__ __launch_bounds__(256) void kqv_mma(
        const float* __restrict__ x,
        const float* __restrict__ Wk, const float* __restrict__ bk,
        const float* __restrict__ Wq, const float* __restrict__ bq,
        const float* __restrict__ Wv, const float* __restrict__ bv,
        const void* __restrict__ slp) {
    extern __shared__ float sm[];
    float* xs   = sm + KQ_XS;
    float* Wsm  = sm + KQ_WS;
    float* stg  = sm + KQ_STG;
    float* bias = sm + KQ_BIA;

    const int tid = threadIdx.x;
    const int lane = tid & 31;
    const int wid = tid >> 5;
    const int g = lane >> 2, q = lane & 3;
    const int b = blockIdx.y;
    const int l0 = blockIdx.x * 128;
    const int r0 = wid * 16;
    const float kscale = rsqrtf(read_len(slp)) * 1.4426950408889634f;

    for (int idx = tid; idx < 56 * 64; idx += 256) {
        int d = idx >> 6, c = idx & 63;
        int pos = (c & ~7) | ((c & 3) << 1) | ((c >> 2) & 1);
        Wsm[d * LDW + pos]        = (d < DD) ? __uint_as_float(f2tf32(Wk[c * DD + d])) : 0.0f;
        Wsm[(56 + d) * LDW + pos] = (d < DD) ? __uint_as_float(f2tf32(Wq[c * DD + d])) : 0.0f;
    }
    for (int idx = tid; idx < 64 * 64; idx += 256) {
        int o = idx >> 6, c = idx & 63;
        int pos = (c & ~7) | ((c & 3) << 1) | ((c >> 2) & 1);
        Wsm[(112 + o) * LDW + pos] = __uint_as_float(f2tf32(Wv[c * CC + o]));
    }
    if (tid < 56)  bias[tid]       = (tid < DD) ? bk[tid] : 0.0f;
    if (tid < 56)  bias[56 + tid]  = (tid < DD) ? bq[tid] : 0.0f;
    if (tid < 64)  bias[112 + tid] = bv[tid];

    for (int idx = tid; idx < 64 * 32; idx += 256) {
        int row = idx >> 5, c4 = idx & 31;
        float4 v = *(const float4*)(x + (size_t)b * CC * LL + (size_t)row * LL + l0 + 4 * c4);
        v.x = __uint_as_float(f2tf32(v.x)); v.y = __uint_as_float(f2tf32(v.y));
        v.z = __uint_as_float(f2tf32(v.z)); v.w = __uint_as_float(f2tf32(v.w));
        *(float4*)&xs[row * LDX + 4 * c4] = v;
    }
    __syncthreads();

    uint32_t xa[8][4];
#pragma unroll
    for (int ks = 0; ks < 8; ks++) {
        xa[ks][0] = __float_as_uint(xs[(8 * ks + q) * LDX + r0 + g]);
        xa[ks][1] = __float_as_uint(xs[(8 * ks + q) * LDX + r0 + g + 8]);
        xa[ks][2] = __float_as_uint(xs[(8 * ks + q + 4) * LDX + r0 + g]);
        xa[ks][3] = __float_as_uint(xs[(8 * ks + q + 4) * LDX + r0 + g + 8]);
    }

    // ---- K ----
#pragma unroll
    for (int nt = 0; nt < 7; nt++) {
        float acc[4] = {0.f, 0.f, 0.f, 0.f};
#pragma unroll
        for (int ks = 0; ks < 8; ks++) {
            float2 bb = *(const float2*)&Wsm[(8 * nt + g) * LDW + 8 * ks + 2 * q];
            mma8(acc, xa[ks], __float_as_uint(bb.x), __float_as_uint(bb.y));
        }
        float b0 = bias[8 * nt + 2 * q], b1 = bias[8 * nt + 2 * q + 1];
        float v0 = acc[0] + b0, v1 = acc[1] + b1, v2 = acc[2] + b0, v3 = acc[3] + b1;
        v0 = (v0 > 0.f) ? v0 : expm1f(v0); v1 = (v1 > 0.f) ? v1 : expm1f(v1);
        v2 = (v2 > 0.f) ? v2 : expm1f(v2); v3 = (v3 > 0.f) ? v3 : expm1f(v3);
        *(float2*)&stg[(r0 + g) * LDW + 8 * nt + 2 * q]     = make_float2(v0, v1);
        *(float2*)&stg[(r0 + g + 8) * LDW + 8 * nt + 2 * q] = make_float2(v2, v3);
    }
    for (int idx = tid; idx < 128 * 8; idx += 256)
        stg[(idx >> 3) * LDW + 56 + (idx & 7)] = 0.0f;
    __syncthreads();
    for (int idx = tid; idx < 128 * 32; idx += 256) {
        int row = idx >> 5, p = (idx & 31) * 2;
        int pl = p & 15;
        int d0 = (p & ~15) + 2 * ((pl >> 2) & 3) + 8 * ((pl >> 1) & 1);
        __half2 h = __floats2half2_rn(stg[row * LDW + d0] * kscale,
                                      stg[row * LDW + d0 + 1] * kscale);
        *(__half2*)(g_Kh + ((size_t)b * LL + l0 + row) * DK + p) = h;
    }
    __syncthreads();

    // ---- Q ----
#pragma unroll
    for (int nt = 0; nt < 7; nt++) {
        float acc[4] = {0.f, 0.f, 0.f, 0.f};
#pragma unroll
        for (int ks = 0; ks < 8; ks++) {
            float2 bb = *(const float2*)&Wsm[(56 + 8 * nt + g) * LDW + 8 * ks + 2 * q];
            mma8(acc, xa[ks], __float_as_uint(bb.x), __float_as_uint(bb.y));
        }
        float b0 = bias[56 + 8 * nt + 2 * q], b1 = bias[56 + 8 * nt + 2 * q + 1];
        float v0 = acc[0] + b0, v1 = acc[1] + b1, v2 = acc[2] + b0, v3 = acc[3] + b1;
        v0 = (v0 > 0.f) ? v0 : expm1f(v0); v1 = (v1 > 0.f) ? v1 : expm1f(v1);
        v2 = (v2 > 0.f) ? v2 : expm1f(v2); v3 = (v3 > 0.f) ? v3 : expm1f(v3);
        *(float2*)&stg[(r0 + g) * LDW + 8 * nt + 2 * q]     = make_float2(v0, v1);
        *(float2*)&stg[(r0 + g + 8) * LDW + 8 * nt + 2 * q] = make_float2(v2, v3);
    }
    for (int idx = tid; idx < 128 * 8; idx += 256)
        stg[(idx >> 3) * LDW + 56 + (idx & 7)] = 0.0f;
    __syncthreads();
    for (int idx = tid; idx < 128 * 32; idx += 256) {
        int row = idx >> 5, p = (idx & 31) * 2;
        int pl = p & 15;
        int d0 = (p & ~15) + 2 * ((pl >> 2) & 3) + 8 * ((pl >> 1) & 1);
        __half2 h = __floats2half2_rn(stg[row * LDW + d0], stg[row * LDW + d0 + 1]);
        *(__half2*)(g_Qh + ((size_t)b * LL + l0 + row) * DK + p) = h;
    }
    __syncthreads();

    // ---- V ----
#pragma unroll
    for (int nt = 0; nt < 8; nt++) {
        float acc[4] = {0.f, 0.f, 0.f, 0.f};
#pragma unroll
        for (int ks = 0; ks < 8; ks++) {
            float2 bb = *(const float2*)&Wsm[(112 + 8 * nt + g) * LDW + 8 * ks + 2 * q];
            mma8(acc, xa[ks], __float_as_uint(bb.x), __float_as_uint(bb.y));
        }
        float b0 = bias[112 + 8 * nt + 2 * q], b1 = bias[112 + 8 * nt + 2 * q + 1];
        *(float2*)&stg[(r0 + g) * LDW + 8 * nt + 2 * q] =
            make_float2(tanhf(acc[0] + b0), tanhf(acc[1] + b1));
        *(float2*)&stg[(r0 + g + 8) * LDW + 8 * nt + 2 * q] =
            make_float2(tanhf(acc[2] + b0), tanhf(acc[3] + b1));
    }
    __syncthreads();
    for (int idx = tid; idx < 128 * 16; idx += 256) {
        int row = idx >> 4, c4 = idx & 15;
        *(float4*)(g_V + ((size_t)b * LL + l0 + row) * CC + 4 * c4) =
            *(float4*)&stg[row * LDW + 4 * c4];
    }
}

// ---------------------------------------------------------------------------
// Kernel 2 (pass1): S fp16 GEMM -> ex2.f16x2 -> column partials (pipelined).
// grid (NLT, BB), 256 thr (8 warps x 16 l rows).
// ---------------------------------------------------------------------------
__global__ __launch_bounds__(256, 3) void pass1(void) {
    extern __shared__ char smraw[];
    __half* Qhs = (__half*)smraw;                    // [128][80]
    float* red  = (float*)(smraw + 128 * LDQH * 2);  // [8][128]

    const int tid = threadIdx.x;
    const int lane = tid & 31;
    const int wid = tid >> 5;
    const int g = lane >> 2, q = lane & 3;
    const int b = blockIdx.y;
    const int l0 = blockIdx.x * TL;
    const int r0 = wid * 16;

    uint32_t Ka[4][4];
#pragma unroll
    for (int ks = 0; ks < 4; ks++) {
        uint2 lo = *(const uint2*)(g_Kh + ((size_t)b * LL + l0 + r0 + g) * DK + 16 * ks + 4 * q);
        uint2 hi = *(const uint2*)(g_Kh + ((size_t)b * LL + l0 + r0 + g + 8) * DK + 16 * ks + 4 * q);
        Ka[ks][0] = lo.x; Ka[ks][2] = lo.y;
        Ka[ks][1] = hi.x; Ka[ks][3] = hi.y;
    }

    for (int mt = 0; mt < NMT; mt++) {
        const int m0 = mt * 128;
        __syncthreads();
        for (int idx = tid; idx < 128 * 8; idx += 256) {
            int row = idx >> 3, c8 = idx & 7;
            *(uint4*)&Qhs[row * LDQH + 8 * c8] =
                *(const uint4*)(g_Qh + ((size_t)b * LL + m0 + row) * DK + 8 * c8);
        }
        __syncthreads();

        float a0[4], a1[4], n0[4], n1[4];
        gemm1_tile(Qhs, 0, Ka, g, q, a0, a1);

#pragma unroll
        for (int t = 0; t < 8; t++) {
            uint32_t px0 = ex2h2(packh2(a0[0], a0[1]));
            uint32_t px1 = ex2h2(packh2(a0[2], a0[3]));
            uint32_t py0 = ex2h2(packh2(a1[0], a1[1]));
            uint32_t py1 = ex2h2(packh2(a1[2], a1[3]));

            if (t < 7) gemm1_tile(Qhs, t + 1, Ka, g, q, n0, n1);   // fills exp/shfl shadow

            __half2 h0 = __hadd2(*(__half2*)&px0, *(__half2*)&px1);
            __half2 h1 = __hadd2(*(__half2*)&py0, *(__half2*)&py1);
#pragma unroll
            for (int off = 4; off < 32; off <<= 1) {
                uint32_t u0 = __shfl_xor_sync(0xFFFFFFFFu, *(uint32_t*)&h0, off);
                uint32_t u1 = __shfl_xor_sync(0xFFFFFFFFu, *(uint32_t*)&h1, off);
                h0 = __hadd2(h0, *(__half2*)&u0);
                h1 = __hadd2(h1, *(__half2*)&u1);
            }
            if (lane < 4) {
                float2 f0 = __half22float2(h0);
                float2 f1 = __half22float2(h1);
                red[wid * 128 + 16 * t + 2 * q]         = f0.x;
                red[wid * 128 + 16 * t + 2 * q + 1]     = f0.y;
                red[wid * 128 + 16 * t + 8 + 2 * q]     = f1.x;
                red[wid * 128 + 16 * t + 8 + 2 * q + 1] = f1.y;
            }
#pragma unroll
            for (int e = 0; e < 4; e++) { a0[e] = n0[e]; a1[e] = n1[e]; }
        }
        __syncthreads();
        if (tid < 128) {
            float s = 0.f;
#pragma unroll
            for (int w = 0; w < 8; w++) s += red[w * 128 + tid];
            g_part[((size_t)blockIdx.x * BB + b) * LL + m0 + tid] = s;
        }
    }
}

// ---------------------------------------------------------------------------
// Kernel 3: cinv; V' = fp16(V*cinv) transposed [c][m'] perm16.
// ---------------------------------------------------------------------------
__global__ void prep_kernel() {
    __shared__ float ci[64];
    __shared__ float vt[64 * 68];
    const int tid = threadIdx.x;
    const int b = blockIdx.y;
    const int m0 = blockIdx.x * 64;

    if (tid < 64) {
        float s = 0.0f;
#pragma unroll
        for (int lt = 0; lt < NLT; lt++)
            s += g_part[((size_t)lt * BB + b) * LL + m0 + tid];
        ci[tid] = 1.0f / s;
    }
    for (int idx = tid; idx < 64 * 16; idx += 256) {
        int row = idx >> 4, c4 = idx & 15;
        *(float4*)&vt[row * 68 + 4 * c4] =
            *(const float4*)(g_V + ((size_t)b * LL + m0 + row) * CC + 4 * c4);
    }
    __syncthreads();
    for (int idx = tid; idx < 64 * 32; idx += 256) {
        int c = idx >> 5, jp = idx & 31;
        int m = 16 * (jp >> 3) + 8 * (jp & 1) + 2 * ((jp >> 1) & 3);
        __half2 hv = __floats2half2_rn(vt[m * 68 + c] * ci[m],
                                       vt[(m + 1) * 68 + c] * ci[m + 1]);
        *(__half2*)(g_Vph + ((size_t)b * CC + c) * LL + m0 + 2 * jp) = hv;
    }
}

// ---------------------------------------------------------------------------
// Kernel 4 (pass2): fused S GEMM -> exp -> Y GEMM with 2x B-fragment reuse.
// grid (NLT, BB), 128 thr (4 warps x 32 rows). Group-A K fragments cached in
// registers; group-B K fragments re-loaded per t from global (L1-resident,
// asm volatile prevents hoisting) to fit 128 regs -> 4 CTAs/SM.
// ---------------------------------------------------------------------------
__global__ __launch_bounds__(128, 4) void pass2(float* __restrict__ out) {
    extern __shared__ char smraw[];
    __half* Qhs = (__half*)smraw;                          // [128][80]
    __half* Vhs = (__half*)(smraw + 128 * LDQH * 2);       // [64][144]

    const int tid = threadIdx.x;
    const int lane = tid & 31;
    const int wid = tid >> 5;
    const int g = lane >> 2, q = lane & 3;
    const int b = blockIdx.y;
    const int l0 = blockIdx.x * TL;
    const int r0 = wid * 32;

    // Group A K fragments: registers (rows r0+g, r0+8+g)
    uint32_t Ka0[4][4];
#pragma unroll
    for (int ks = 0; ks < 4; ks++) {
        uint2 lo = *(const uint2*)(g_Kh + ((size_t)b * LL + l0 + r0 + g) * DK + 16 * ks + 4 * q);
        uint2 hi = *(const uint2*)(g_Kh + ((size_t)b * LL + l0 + r0 + g + 8) * DK + 16 * ks + 4 * q);
        Ka0[ks][0] = lo.x; Ka0[ks][2] = lo.y;
        Ka0[ks][1] = hi.x; Ka0[ks][3] = hi.y;
    }
    // Group B K fragment base pointers (rows r0+16+g, r0+24+g)
    const __half* kb1g = g_Kh + ((size_t)b * LL + l0 + r0 + 16 + g) * DK + 4 * q;
    const __half* kb1h = g_Kh + ((size_t)b * LL + l0 + r0 + 24 + g) * DK + 4 * q;

    float y0[8][4], y1[8][4];
#pragma unroll
    for (int n = 0; n < 8; n++)
#pragma unroll
        for (int e = 0; e < 4; e++) { y0[n][e] = 0.f; y1[n][e] = 0.f; }

    for (int mt = 0; mt < NMT; mt++) {
        const int m0 = mt * 128;
        __syncthreads();
        for (int idx = tid; idx < 128 * 8; idx += 128) {
            int row = idx >> 3, c8 = idx & 7;
            *(uint4*)&Qhs[row * LDQH + 8 * c8] =
                *(const uint4*)(g_Qh + ((size_t)b * LL + m0 + row) * DK + 8 * c8);
        }
        for (int idx = tid; idx < 64 * 16; idx += 128) {
            int row = idx >> 4, j16 = idx & 15;
            *(uint4*)&Vhs[row * LDVH + 8 * j16] =
                *(const uint4*)(g_Vph + ((size_t)b * CC + row) * LL + m0 + 8 * j16);
        }
        __syncthreads();

#pragma unroll
        for (int t = 0; t < 8; t++) {
            // Reload group-B K fragments (L1 hit; volatile stops hoisting)
            uint32_t Kb[4][4];
#pragma unroll
            for (int ks = 0; ks < 4; ks++) {
                uint32_t u0, u1, v0, v1;
                asm volatile("ld.global.nc.v2.u32 {%0,%1}, [%2];"
                             : "=r"(u0), "=r"(u1) : "l"(kb1g + 16 * ks));
                asm volatile("ld.global.nc.v2.u32 {%0,%1}, [%2];"
                             : "=r"(v0), "=r"(v1) : "l"(kb1h + 16 * ks));
                Kb[ks][0] = u0; Kb[ks][2] = u1;
                Kb[ks][1] = v0; Kb[ks][3] = v1;
            }

            // GEMM1 for both row-groups; B-frags (Q) loaded once
            float a0A[4] = {0.f,0.f,0.f,0.f}, a1A[4] = {0.f,0.f,0.f,0.f};
            float a0B[4] = {0.f,0.f,0.f,0.f}, a1B[4] = {0.f,0.f,0.f,0.f};
#pragma unroll
            for (int ks = 0; ks < 4; ks++) {
                uint2 q0 = *(const uint2*)&Qhs[(16 * t + g) * LDQH + 16 * ks + 4 * q];
                uint2 q1 = *(const uint2*)&Qhs[(16 * t + 8 + g) * LDQH + 16 * ks + 4 * q];
                mma16(a0A, Ka0[ks][0], Ka0[ks][1], Ka0[ks][2], Ka0[ks][3], q0.x, q0.y);
                mma16(a1A, Ka0[ks][0], Ka0[ks][1], Ka0[ks][2], Ka0[ks][3], q1.x, q1.y);
                mma16(a0B, Kb[ks][0], Kb[ks][1], Kb[ks][2], Kb[ks][3], q0.x, q0.y);
                mma16(a1B, Kb[ks][0], Kb[ks][1], Kb[ks][2], Kb[ks][3], q1.x, q1.y);
            }
            // exp -> fp16 A fragments (layout identity)
            uint32_t pxA0 = ex2h2(packh2(a0A[0], a0A[1]));
            uint32_t pxA1 = ex2h2(packh2(a0A[2], a0A[3]));
            uint32_t pyA0 = ex2h2(packh2(a1A[0], a1A[1]));
            uint32_t pyA1 = ex2h2(packh2(a1A[2], a1A[3]));
            uint32_t pxB0 = ex2h2(packh2(a0B[0], a0B[1]));
            uint32_t pxB1 = ex2h2(packh2(a0B[2], a0B[3]));
            uint32_t pyB0 = ex2h2(packh2(a1B[0], a1B[1]));
            uint32_t pyB1 = ex2h2(packh2(a1B[2], a1B[3]));

            // GEMM2 for both row-groups; B-frags (V') loaded once
#pragma unroll
            for (int n = 0; n < 8; n++) {
                uint2 bb = *(const uint2*)&Vhs[(8 * n + g) * LDVH + 16 * t + 4 * q];
                mma16(y0[n], pxA0, pxA1, pyA0, pyA1, bb.x, bb.y);
                mma16(y1[n], pxB0, pxB1, pyB0, pyB1, bb.x, bb.y);
            }
        }
    }

    float* ob0 = out + ((size_t)b * LL + l0 + r0) * CC;
    float* ob1 = out + ((size_t)b * LL + l0 + r0 + 16) * CC;
#pragma unroll
    for (int n = 0; n < 8; n++) {
        *(float2*)&ob0[(size_t)g * CC + 8 * n + 2 * q]       = make_float2(y0[n][0], y0[n][1]);
        *(float2*)&ob0[(size_t)(g + 8) * CC + 8 * n + 2 * q] = make_float2(y0[n][2], y0[n][3]);
        *(float2*)&ob1[(size_t)g * CC + 8 * n + 2 * q]       = make_float2(y1[n][0], y1[n][1]);
        *(float2*)&ob1[(size_t)(g + 8) * CC + 8 * n + 2 * q] = make_float2(y1[n][2], y1[n][3]);
    }
}

// ---------------------------------------------------------------------------
extern "C" void kernel_launch(void* const* d_in, const int* in_sizes, int n_in,
                              void* d_out, int out_size) {
    const float* x  = (const float*)d_in[0];
    const float* Wk = (const float*)d_in[1];
    const float* bk = (const float*)d_in[2];
    const float* Wq = (const float*)d_in[3];
    const float* bq = (const float*)d_in[4];
    const float* Wv = (const float*)d_in[5];
    const float* bv = (const float*)d_in[6];
    const void*  sl = (const void*)d_in[7];
    float* out = (float*)d_out;

    const int kq_smem = KQ_TOT * (int)sizeof(float);
    const int p1_smem = 128 * LDQH * 2 + 8 * 128 * (int)sizeof(float);
    const int p2_smem = 128 * LDQH * 2 + 64 * LDVH * 2;

    static bool attr_set = false;
    if (!attr_set) {
        cudaFuncSetAttribute(kqv_mma, cudaFuncAttributeMaxDynamicSharedMemorySize, kq_smem);
        cudaFuncSetAttribute(pass1,   cudaFuncAttributeMaxDynamicSharedMemorySize, p1_smem);
        cudaFuncSetAttribute(pass2,   cudaFuncAttributeMaxDynamicSharedMemorySize, p2_smem);
        attr_set = true;
    }

    dim3 g1(NLT, BB);
    kqv_mma<<<g1, 256, kq_smem>>>(x, Wk, bk, Wq, bq, Wv, bv, sl);

    dim3 g2(NLT, BB);
    pass1<<<g2, 256, p1_smem>>>();

    dim3 g3(LL / 64, BB);
    prep_kernel<<<g3, 256>>>();

    dim3 g4(NLT, BB);
    pass2<<<g4, 128, p2_smem>>>(out);
}

// round 13
// speedup vs baseline: 1.4138x; 1.4138x over previous
#include <cuda_runtime.h>
#include <cuda_fp16.h>
#include <math.h>
#include <stdint.h>

// Problem constants
#define BB 32
#define CC 64
#define LL 2048
#define DD 50
#define DK 64
#define TL 128
#define NLT (LL/TL)    // 16
#define NMT (LL/128)   // 16

// Scratch (device globals — allocation is forbidden)
// g_Kh/g_Qh: fp16, d interleaved within 16-chunks: pos 4q..4q+3 hold d = 2q,2q+1,2q+8,2q+9.
// g_Kh pre-scaled by log2e/sqrt(sample_len).
__device__ __half g_Kh[BB*LL*DK];
__device__ __half g_Qh[BB*LL*DK];
__device__ float  g_V[BB*LL*CC];          // tanh(xWv+bv), [m][c] fp32
__device__ __half g_Vph[BB*CC*LL];        // V' = V*cinv, [c][m'] perm16 on m
__device__ float  g_part[NLT*BB*LL];      // per-ltile column partials

#define LDQH 80        // halves; 40 words -> phase-conflict-free LDS.64
#define LDVH 144       // halves

__device__ __forceinline__ float read_len(const void* p) {
    int i = *(const int*)p;
    if (i > 0 && i < (1 << 24)) return (float)i;
    return __int_as_float(i);
}
__device__ __forceinline__ uint32_t f2tf32(float x) {
    uint32_t u;
    asm("cvt.rna.tf32.f32 %0, %1;" : "=r"(u) : "f"(x));
    return u;
}
__device__ __forceinline__ uint32_t packh2(float lo, float hi) {
    __half2 h = __floats2half2_rn(lo, hi);
    return *(uint32_t*)&h;
}
__device__ __forceinline__ uint32_t ex2h2(uint32_t v) {
    uint32_t r;
    asm("ex2.approx.f16x2 %0, %1;" : "=r"(r) : "r"(v));
    return r;
}
// D += A(16x8 tf32) * B(8x8 tf32)
__device__ __forceinline__ void mma8(float* d, const uint32_t* a, uint32_t b0, uint32_t b1) {
    asm volatile("mma.sync.aligned.m16n8k8.row.col.f32.tf32.tf32.f32 "
                 "{%0,%1,%2,%3}, {%4,%5,%6,%7}, {%8,%9}, {%0,%1,%2,%3};"
                 : "+f"(d[0]), "+f"(d[1]), "+f"(d[2]), "+f"(d[3])
                 : "r"(a[0]), "r"(a[1]), "r"(a[2]), "r"(a[3]), "r"(b0), "r"(b1));
}
// D += A(16x16 f16) * B(16x8 f16)
__device__ __forceinline__ void mma16(float* d, uint32_t a0, uint32_t a1, uint32_t a2,
                                      uint32_t a3, uint32_t b0, uint32_t b1) {
    asm volatile("mma.sync.aligned.m16n8k16.row.col.f32.f16.f16.f32 "
                 "{%0,%1,%2,%3}, {%4,%5,%6,%7}, {%8,%9}, {%0,%1,%2,%3};"
                 : "+f"(d[0]), "+f"(d[1]), "+f"(d[2]), "+f"(d[3])
                 : "r"(a0), "r"(a1), "r"(a2), "r"(a3), "r"(b0), "r"(b1));
}

// S tile GEMM1: rows (via Ka), cols 16t..16t+15, from Qhs
__device__ __forceinline__ void gemm1_tile(const __half* Qhs, int t,
                                           const uint32_t Ka[4][4], int g, int q,
                                           float* a0, float* a1) {
#pragma unroll
    for (int e = 0; e < 4; e++) { a0[e] = 0.f; a1[e] = 0.f; }
#pragma unroll
    for (int ks = 0; ks < 4; ks++) {
        uint2 q0 = *(const uint2*)&Qhs[(16 * t + g) * LDQH + 16 * ks + 4 * q];
        uint2 q1 = *(const uint2*)&Qhs[(16 * t + 8 + g) * LDQH + 16 * ks + 4 * q];
        mma16(a0, Ka[ks][0], Ka[ks][1], Ka[ks][2], Ka[ks][3], q0.x, q0.y);
        mma16(a1, Ka[ks][0], Ka[ks][1], Ka[ks][2], Ka[ks][3], q1.x, q1.y);
    }
}

// ---------------------------------------------------------------------------
// Kernel 1: projections via tf32 mma8. grid (16, 32), 256 thr (8 warps x 16 l).
// ---------------------------------------------------------------------------
#define KQ_XS   0
#define KQ_WS   (KQ_XS + 64*136)
#define KQ_STG  (KQ_WS + 176*72)
#define KQ_BIA  (KQ_STG + 128*72)
#define KQ_TOT  (KQ_BIA + 176)
#define LDX 136
#define LDW 72

__global__ __launch_bounds__(256) void kqv_mma(
        const float* __restrict__ x,
        const float* __restrict__ Wk, const float* __restrict__ bk,
        const float* __restrict__ Wq, const float* __restrict__ bq,
        const float* __restrict__ Wv, const float* __restrict__ bv,
        const void* __restrict__ slp) {
    extern __shared__ float sm[];
    float* xs   = sm + KQ_XS;
    float* Wsm  = sm + KQ_WS;
    float* stg  = sm + KQ_STG;
    float* bias = sm + KQ_BIA;

    const int tid = threadIdx.x;
    const int lane = tid & 31;
    const int wid = tid >> 5;
    const int g = lane >> 2, q = lane & 3;
    const int b = blockIdx.y;
    const int l0 = blockIdx.x * 128;
    const int r0 = wid * 16;
    const float kscale = rsqrtf(read_len(slp)) * 1.4426950408889634f;

    for (int idx = tid; idx < 56 * 64; idx += 256) {
        int d = idx >> 6, c = idx & 63;
        int pos = (c & ~7) | ((c & 3) << 1) | ((c >> 2) & 1);
        Wsm[d * LDW + pos]        = (d < DD) ? __uint_as_float(f2tf32(Wk[c * DD + d])) : 0.0f;
        Wsm[(56 + d) * LDW + pos] = (d < DD) ? __uint_as_float(f2tf32(Wq[c * DD + d])) : 0.0f;
    }
    for (int idx = tid; idx < 64 * 64; idx += 256) {
        int o = idx >> 6, c = idx & 63;
        int pos = (c & ~7) | ((c & 3) << 1) | ((c >> 2) & 1);
        Wsm[(112 + o) * LDW + pos] = __uint_as_float(f2tf32(Wv[c * CC + o]));
    }
    if (tid < 56)  bias[tid]       = (tid < DD) ? bk[tid] : 0.0f;
    if (tid < 56)  bias[56 + tid]  = (tid < DD) ? bq[tid] : 0.0f;
    if (tid < 64)  bias[112 + tid] = bv[tid];

    for (int idx = tid; idx < 64 * 32; idx += 256) {
        int row = idx >> 5, c4 = idx & 31;
        float4 v = *(const float4*)(x + (size_t)b * CC * LL + (size_t)row * LL + l0 + 4 * c4);
        v.x = __uint_as_float(f2tf32(v.x)); v.y = __uint_as_float(f2tf32(v.y));
        v.z = __uint_as_float(f2tf32(v.z)); v.w = __uint_as_float(f2tf32(v.w));
        *(float4*)&xs[row * LDX + 4 * c4] = v;
    }
    __syncthreads();

    uint32_t xa[8][4];
#pragma unroll
    for (int ks = 0; ks < 8; ks++) {
        xa[ks][0] = __float_as_uint(xs[(8 * ks + q) * LDX + r0 + g]);
        xa[ks][1] = __float_as_uint(xs[(8 * ks + q) * LDX + r0 + g + 8]);
        xa[ks][2] = __float_as_uint(xs[(8 * ks + q + 4) * LDX + r0 + g]);
        xa[ks][3] = __float_as_uint(xs[(8 * ks + q + 4) * LDX + r0 + g + 8]);
    }

    // ---- K ----
#pragma unroll
    for (int nt = 0; nt < 7; nt++) {
        float acc[4] = {0.f, 0.f, 0.f, 0.f};
#pragma unroll
        for (int ks = 0; ks < 8; ks++) {
            float2 bb = *(const float2*)&Wsm[(8 * nt + g) * LDW + 8 * ks + 2 * q];
            mma8(acc, xa[ks], __float_as_uint(bb.x), __float_as_uint(bb.y));
        }
        float b0 = bias[8 * nt + 2 * q], b1 = bias[8 * nt + 2 * q + 1];
        float v0 = acc[0] + b0, v1 = acc[1] + b1, v2 = acc[2] + b0, v3 = acc[3] + b1;
        v0 = (v0 > 0.f) ? v0 : expm1f(v0); v1 = (v1 > 0.f) ? v1 : expm1f(v1);
        v2 = (v2 > 0.f) ? v2 : expm1f(v2); v3 = (v3 > 0.f) ? v3 : expm1f(v3);
        *(float2*)&stg[(r0 + g) * LDW + 8 * nt + 2 * q]     = make_float2(v0, v1);
        *(float2*)&stg[(r0 + g + 8) * LDW + 8 * nt + 2 * q] = make_float2(v2, v3);
    }
    for (int idx = tid; idx < 128 * 8; idx += 256)
        stg[(idx >> 3) * LDW + 56 + (idx & 7)] = 0.0f;
    __syncthreads();
    for (int idx = tid; idx < 128 * 32; idx += 256) {
        int row = idx >> 5, p = (idx & 31) * 2;
        int pl = p & 15;
        int d0 = (p & ~15) + 2 * ((pl >> 2) & 3) + 8 * ((pl >> 1) & 1);
        __half2 h = __floats2half2_rn(stg[row * LDW + d0] * kscale,
                                      stg[row * LDW + d0 + 1] * kscale);
        *(__half2*)(g_Kh + ((size_t)b * LL + l0 + row) * DK + p) = h;
    }
    __syncthreads();

    // ---- Q ----
#pragma unroll
    for (int nt = 0; nt < 7; nt++) {
        float acc[4] = {0.f, 0.f, 0.f, 0.f};
#pragma unroll
        for (int ks = 0; ks < 8; ks++) {
            float2 bb = *(const float2*)&Wsm[(56 + 8 * nt + g) * LDW + 8 * ks + 2 * q];
            mma8(acc, xa[ks], __float_as_uint(bb.x), __float_as_uint(bb.y));
        }
        float b0 = bias[56 + 8 * nt + 2 * q], b1 = bias[56 + 8 * nt + 2 * q + 1];
        float v0 = acc[0] + b0, v1 = acc[1] + b1, v2 = acc[2] + b0, v3 = acc[3] + b1;
        v0 = (v0 > 0.f) ? v0 : expm1f(v0); v1 = (v1 > 0.f) ? v1 : expm1f(v1);
        v2 = (v2 > 0.f) ? v2 : expm1f(v2); v3 = (v3 > 0.f) ? v3 : expm1f(v3);
        *(float2*)&stg[(r0 + g) * LDW + 8 * nt + 2 * q]     = make_float2(v0, v1);
        *(float2*)&stg[(r0 + g + 8) * LDW + 8 * nt + 2 * q] = make_float2(v2, v3);
    }
    for (int idx = tid; idx < 128 * 8; idx += 256)
        stg[(idx >> 3) * LDW + 56 + (idx & 7)] = 0.0f;
    __syncthreads();
    for (int idx = tid; idx < 128 * 32; idx += 256) {
        int row = idx >> 5, p = (idx & 31) * 2;
        int pl = p & 15;
        int d0 = (p & ~15) + 2 * ((pl >> 2) & 3) + 8 * ((pl >> 1) & 1);
        __half2 h = __floats2half2_rn(stg[row * LDW + d0], stg[row * LDW + d0 + 1]);
        *(__half2*)(g_Qh + ((size_t)b * LL + l0 + row) * DK + p) = h;
    }
    __syncthreads();

    // ---- V ----
#pragma unroll
    for (int nt = 0; nt < 8; nt++) {
        float acc[4] = {0.f, 0.f, 0.f, 0.f};
#pragma unroll
        for (int ks = 0; ks < 8; ks++) {
            float2 bb = *(const float2*)&Wsm[(112 + 8 * nt + g) * LDW + 8 * ks + 2 * q];
            mma8(acc, xa[ks], __float_as_uint(bb.x), __float_as_uint(bb.y));
        }
        float b0 = bias[112 + 8 * nt + 2 * q], b1 = bias[112 + 8 * nt + 2 * q + 1];
        *(float2*)&stg[(r0 + g) * LDW + 8 * nt + 2 * q] =
            make_float2(tanhf(acc[0] + b0), tanhf(acc[1] + b1));
        *(float2*)&stg[(r0 + g + 8) * LDW + 8 * nt + 2 * q] =
            make_float2(tanhf(acc[2] + b0), tanhf(acc[3] + b1));
    }
    __syncthreads();
    for (int idx = tid; idx < 128 * 16; idx += 256) {
        int row = idx >> 4, c4 = idx & 15;
        *(float4*)(g_V + ((size_t)b * LL + l0 + row) * CC + 4 * c4) =
            *(float4*)&stg[row * LDW + 4 * c4];
    }
}

// ---------------------------------------------------------------------------
// Kernel 2 (pass1): S fp16 GEMM -> ex2.f16x2 -> column partials (pipelined).
// grid (NLT, BB), 256 thr (8 warps x 16 l rows).
// ---------------------------------------------------------------------------
__global__ __launch_bounds__(256, 3) void pass1(void) {
    extern __shared__ char smraw[];
    __half* Qhs = (__half*)smraw;                    // [128][80]
    float* red  = (float*)(smraw + 128 * LDQH * 2);  // [8][128]

    const int tid = threadIdx.x;
    const int lane = tid & 31;
    const int wid = tid >> 5;
    const int g = lane >> 2, q = lane & 3;
    const int b = blockIdx.y;
    const int l0 = blockIdx.x * TL;
    const int r0 = wid * 16;

    uint32_t Ka[4][4];
#pragma unroll
    for (int ks = 0; ks < 4; ks++) {
        uint2 lo = *(const uint2*)(g_Kh + ((size_t)b * LL + l0 + r0 + g) * DK + 16 * ks + 4 * q);
        uint2 hi = *(const uint2*)(g_Kh + ((size_t)b * LL + l0 + r0 + g + 8) * DK + 16 * ks + 4 * q);
        Ka[ks][0] = lo.x; Ka[ks][2] = lo.y;
        Ka[ks][1] = hi.x; Ka[ks][3] = hi.y;
    }

    for (int mt = 0; mt < NMT; mt++) {
        const int m0 = mt * 128;
        __syncthreads();
        for (int idx = tid; idx < 128 * 8; idx += 256) {
            int row = idx >> 3, c8 = idx & 7;
            *(uint4*)&Qhs[row * LDQH + 8 * c8] =
                *(const uint4*)(g_Qh + ((size_t)b * LL + m0 + row) * DK + 8 * c8);
        }
        __syncthreads();

        float a0[4], a1[4], n0[4], n1[4];
        gemm1_tile(Qhs, 0, Ka, g, q, a0, a1);

#pragma unroll
        for (int t = 0; t < 8; t++) {
            uint32_t px0 = ex2h2(packh2(a0[0], a0[1]));
            uint32_t px1 = ex2h2(packh2(a0[2], a0[3]));
            uint32_t py0 = ex2h2(packh2(a1[0], a1[1]));
            uint32_t py1 = ex2h2(packh2(a1[2], a1[3]));

            if (t < 7) gemm1_tile(Qhs, t + 1, Ka, g, q, n0, n1);   // fills exp/shfl shadow

            __half2 h0 = __hadd2(*(__half2*)&px0, *(__half2*)&px1);
            __half2 h1 = __hadd2(*(__half2*)&py0, *(__half2*)&py1);
#pragma unroll
            for (int off = 4; off < 32; off <<= 1) {
                uint32_t u0 = __shfl_xor_sync(0xFFFFFFFFu, *(uint32_t*)&h0, off);
                uint32_t u1 = __shfl_xor_sync(0xFFFFFFFFu, *(uint32_t*)&h1, off);
                h0 = __hadd2(h0, *(__half2*)&u0);
                h1 = __hadd2(h1, *(__half2*)&u1);
            }
            if (lane < 4) {
                float2 f0 = __half22float2(h0);
                float2 f1 = __half22float2(h1);
                red[wid * 128 + 16 * t + 2 * q]         = f0.x;
                red[wid * 128 + 16 * t + 2 * q + 1]     = f0.y;
                red[wid * 128 + 16 * t + 8 + 2 * q]     = f1.x;
                red[wid * 128 + 16 * t + 8 + 2 * q + 1] = f1.y;
            }
#pragma unroll
            for (int e = 0; e < 4; e++) { a0[e] = n0[e]; a1[e] = n1[e]; }
        }
        __syncthreads();
        if (tid < 128) {
            float s = 0.f;
#pragma unroll
            for (int w = 0; w < 8; w++) s += red[w * 128 + tid];
            g_part[((size_t)blockIdx.x * BB + b) * LL + m0 + tid] = s;
        }
    }
}

// ---------------------------------------------------------------------------
// Kernel 3: cinv; V' = fp16(V*cinv) transposed [c][m'] perm16.
// ---------------------------------------------------------------------------
__global__ void prep_kernel() {
    __shared__ float ci[64];
    __shared__ float vt[64 * 68];
    const int tid = threadIdx.x;
    const int b = blockIdx.y;
    const int m0 = blockIdx.x * 64;

    if (tid < 64) {
        float s = 0.0f;
#pragma unroll
        for (int lt = 0; lt < NLT; lt++)
            s += g_part[((size_t)lt * BB + b) * LL + m0 + tid];
        ci[tid] = 1.0f / s;
    }
    for (int idx = tid; idx < 64 * 16; idx += 256) {
        int row = idx >> 4, c4 = idx & 15;
        *(float4*)&vt[row * 68 + 4 * c4] =
            *(const float4*)(g_V + ((size_t)b * LL + m0 + row) * CC + 4 * c4);
    }
    __syncthreads();
    for (int idx = tid; idx < 64 * 32; idx += 256) {
        int c = idx >> 5, jp = idx & 31;
        int m = 16 * (jp >> 3) + 8 * (jp & 1) + 2 * ((jp >> 1) & 3);
        __half2 hv = __floats2half2_rn(vt[m * 68 + c] * ci[m],
                                       vt[(m + 1) * 68 + c] * ci[m + 1]);
        *(__half2*)(g_Vph + ((size_t)b * CC + c) * LL + m0 + 2 * jp) = hv;
    }
}

// ---------------------------------------------------------------------------
// Kernel 4 (pass2): fused S GEMM -> exp -> Y GEMM, R11 per-warp structure,
// but TL=64: 2 warps x 32 rows, 64 threads, grid (32, 32) = 1024 CTAs.
// 5 CTAs/SM (smem-limited) -> 740 slots; halved CTA duration fixes the
// 2-wave quantization loss of the 512-CTA version.
// ---------------------------------------------------------------------------
__global__ __launch_bounds__(64, 5) void pass2(float* __restrict__ out) {
    extern __shared__ char smraw[];
    __half* Qhs = (__half*)smraw;                          // [128][80]
    __half* Vhs = (__half*)(smraw + 128 * LDQH * 2);       // [64][144]

    const int tid = threadIdx.x;
    const int lane = tid & 31;
    const int wid = tid >> 5;          // 0..1
    const int g = lane >> 2, q = lane & 3;
    const int b = blockIdx.y;
    const int l0 = blockIdx.x * 64;
    const int r0 = wid * 32;

    uint32_t Ka0[4][4], Ka1[4][4];
#pragma unroll
    for (int ks = 0; ks < 4; ks++) {
        uint2 lo = *(const uint2*)(g_Kh + ((size_t)b * LL + l0 + r0 + g) * DK + 16 * ks + 4 * q);
        uint2 hi = *(const uint2*)(g_Kh + ((size_t)b * LL + l0 + r0 + g + 8) * DK + 16 * ks + 4 * q);
        Ka0[ks][0] = lo.x; Ka0[ks][2] = lo.y;
        Ka0[ks][1] = hi.x; Ka0[ks][3] = hi.y;
        uint2 lo1 = *(const uint2*)(g_Kh + ((size_t)b * LL + l0 + r0 + 16 + g) * DK + 16 * ks + 4 * q);
        uint2 hi1 = *(const uint2*)(g_Kh + ((size_t)b * LL + l0 + r0 + 24 + g) * DK + 16 * ks + 4 * q);
        Ka1[ks][0] = lo1.x; Ka1[ks][2] = lo1.y;
        Ka1[ks][1] = hi1.x; Ka1[ks][3] = hi1.y;
    }

    float y0[8][4], y1[8][4];
#pragma unroll
    for (int n = 0; n < 8; n++)
#pragma unroll
        for (int e = 0; e < 4; e++) { y0[n][e] = 0.f; y1[n][e] = 0.f; }

    for (int mt = 0; mt < NMT; mt++) {
        const int m0 = mt * 128;
        __syncthreads();
        for (int idx = tid; idx < 128 * 8; idx += 64) {
            int row = idx >> 3, c8 = idx & 7;
            *(uint4*)&Qhs[row * LDQH + 8 * c8] =
                *(const uint4*)(g_Qh + ((size_t)b * LL + m0 + row) * DK + 8 * c8);
        }
        for (int idx = tid; idx < 64 * 16; idx += 64) {
            int row = idx >> 4, j16 = idx & 15;
            *(uint4*)&Vhs[row * LDVH + 8 * j16] =
                *(const uint4*)(g_Vph + ((size_t)b * CC + row) * LL + m0 + 8 * j16);
        }
        __syncthreads();

#pragma unroll
        for (int t = 0; t < 8; t++) {
            // GEMM1 for both row-groups; B-frags (Q) loaded once
            float a0A[4] = {0.f,0.f,0.f,0.f}, a1A[4] = {0.f,0.f,0.f,0.f};
            float a0B[4] = {0.f,0.f,0.f,0.f}, a1B[4] = {0.f,0.f,0.f,0.f};
#pragma unroll
            for (int ks = 0; ks < 4; ks++) {
                uint2 q0 = *(const uint2*)&Qhs[(16 * t + g) * LDQH + 16 * ks + 4 * q];
                uint2 q1 = *(const uint2*)&Qhs[(16 * t + 8 + g) * LDQH + 16 * ks + 4 * q];
                mma16(a0A, Ka0[ks][0], Ka0[ks][1], Ka0[ks][2], Ka0[ks][3], q0.x, q0.y);
                mma16(a1A, Ka0[ks][0], Ka0[ks][1], Ka0[ks][2], Ka0[ks][3], q1.x, q1.y);
                mma16(a0B, Ka1[ks][0], Ka1[ks][1], Ka1[ks][2], Ka1[ks][3], q0.x, q0.y);
                mma16(a1B, Ka1[ks][0], Ka1[ks][1], Ka1[ks][2], Ka1[ks][3], q1.x, q1.y);
            }
            // exp -> fp16 A fragments (layout identity)
            uint32_t pxA0 = ex2h2(packh2(a0A[0], a0A[1]));
            uint32_t pxA1 = ex2h2(packh2(a0A[2], a0A[3]));
            uint32_t pyA0 = ex2h2(packh2(a1A[0], a1A[1]));
            uint32_t pyA1 = ex2h2(packh2(a1A[2], a1A[3]));
            uint32_t pxB0 = ex2h2(packh2(a0B[0], a0B[1]));
            uint32_t pxB1 = ex2h2(packh2(a0B[2], a0B[3]));
            uint32_t pyB0 = ex2h2(packh2(a1B[0], a1B[1]));
            uint32_t pyB1 = ex2h2(packh2(a1B[2], a1B[3]));

            // GEMM2 for both row-groups; B-frags (V') loaded once
#pragma unroll
            for (int n = 0; n < 8; n++) {
                uint2 bb = *(const uint2*)&Vhs[(8 * n + g) * LDVH + 16 * t + 4 * q];
                mma16(y0[n], pxA0, pxA1, pyA0, pyA1, bb.x, bb.y);
                mma16(y1[n], pxB0, pxB1, pyB0, pyB1, bb.x, bb.y);
            }
        }
    }

    float* ob0 = out + ((size_t)b * LL + l0 + r0) * CC;
    float* ob1 = out + ((size_t)b * LL + l0 + r0 + 16) * CC;
#pragma unroll
    for (int n = 0; n < 8; n++) {
        *(float2*)&ob0[(size_t)g * CC + 8 * n + 2 * q]       = make_float2(y0[n][0], y0[n][1]);
        *(float2*)&ob0[(size_t)(g + 8) * CC + 8 * n + 2 * q] = make_float2(y0[n][2], y0[n][3]);
        *(float2*)&ob1[(size_t)g * CC + 8 * n + 2 * q]       = make_float2(y1[n][0], y1[n][1]);
        *(float2*)&ob1[(size_t)(g + 8) * CC + 8 * n + 2 * q] = make_float2(y1[n][2], y1[n][3]);
    }
}

// ---------------------------------------------------------------------------
extern "C" void kernel_launch(void* const* d_in, const int* in_sizes, int n_in,
                              void* d_out, int out_size) {
    const float* x  = (const float*)d_in[0];
    const float* Wk = (const float*)d_in[1];
    const float* bk = (const float*)d_in[2];
    const float* Wq = (const float*)d_in[3];
    const float* bq = (const float*)d_in[4];
    const float* Wv = (const float*)d_in[5];
    const float* bv = (const float*)d_in[6];
    const void*  sl = (const void*)d_in[7];
    float* out = (float*)d_out;

    const int kq_smem = KQ_TOT * (int)sizeof(float);
    const int p1_smem = 128 * LDQH * 2 + 8 * 128 * (int)sizeof(float);
    const int p2_smem = 128 * LDQH * 2 + 64 * LDVH * 2;

    static bool attr_set = false;
    if (!attr_set) {
        cudaFuncSetAttribute(kqv_mma, cudaFuncAttributeMaxDynamicSharedMemorySize, kq_smem);
        cudaFuncSetAttribute(pass1,   cudaFuncAttributeMaxDynamicSharedMemorySize, p1_smem);
        cudaFuncSetAttribute(pass2,   cudaFuncAttributeMaxDynamicSharedMemorySize, p2_smem);
        attr_set = true;
    }

    dim3 g1(NLT, BB);
    kqv_mma<<<g1, 256, kq_smem>>>(x, Wk, bk, Wq, bq, Wv, bv, sl);

    dim3 g2(NLT, BB);
    pass1<<<g2, 256, p1_smem>>>();

    dim3 g3(LL / 64, BB);
    prep_kernel<<<g3, 256>>>();

    dim3 g4(LL / 64, BB);
    pass2<<<g4, 64, p2_smem>>>(out);
}

// round 14
// speedup vs baseline: 1.6864x; 1.1928x over previous
#include <cuda_runtime.h>
#include <cuda_fp16.h>
#include <math.h>
#include <stdint.h>

// Problem constants
#define BB 32
#define CC 64
#define LL 2048
#define DD 50
#define DK 64
#define TL 128
#define NLT (LL/TL)    // 16
#define NMT (LL/128)   // 16

// Scratch (device globals — allocation is forbidden)
// g_Kh/g_Qh: fp16, d interleaved within 16-chunks: pos 4q..4q+3 hold d = 2q,2q+1,2q+8,2q+9.
// g_Kh pre-scaled by log2e/sqrt(sample_len).
__device__ __half g_Kh[BB*LL*DK];
__device__ __half g_Qh[BB*LL*DK];
__device__ float  g_V[BB*LL*CC];          // tanh(xWv+bv), [m][c] fp32
__device__ __half g_Vph[BB*CC*LL];        // V' = V*cinv, [c][m'] perm16 on m
__device__ float  g_part[NLT*BB*LL];      // per-ltile column partials

#define LDQH 80        // pass1 smem leading dim (halves); 40 words -> conflict-free

__device__ __forceinline__ float read_len(const void* p) {
    int i = *(const int*)p;
    if (i > 0 && i < (1 << 24)) return (float)i;
    return __int_as_float(i);
}
__device__ __forceinline__ uint32_t smem_u32(const void* p) {
    uint32_t a;
    asm("{ .reg .u64 t; cvta.to.shared.u64 t, %1; cvt.u32.u64 %0, t; }" : "=r"(a) : "l"(p));
    return a;
}
__device__ __forceinline__ void cpa16(uint32_t dst, const void* src) {
    asm volatile("cp.async.cg.shared.global [%0], [%1], 16;" :: "r"(dst), "l"(src));
}
#define CP_COMMIT() asm volatile("cp.async.commit_group;" ::: "memory")
#define CP_WAIT0()  asm volatile("cp.async.wait_group 0;" ::: "memory")

__device__ __forceinline__ uint32_t f2tf32(float x) {
    uint32_t u;
    asm("cvt.rna.tf32.f32 %0, %1;" : "=r"(u) : "f"(x));
    return u;
}
__device__ __forceinline__ uint32_t packh2(float lo, float hi) {
    __half2 h = __floats2half2_rn(lo, hi);
    return *(uint32_t*)&h;
}
__device__ __forceinline__ uint32_t ex2h2(uint32_t v) {
    uint32_t r;
    asm("ex2.approx.f16x2 %0, %1;" : "=r"(r) : "r"(v));
    return r;
}
// D += A(16x8 tf32) * B(8x8 tf32)
__device__ __forceinline__ void mma8(float* d, const uint32_t* a, uint32_t b0, uint32_t b1) {
    asm volatile("mma.sync.aligned.m16n8k8.row.col.f32.tf32.tf32.f32 "
                 "{%0,%1,%2,%3}, {%4,%5,%6,%7}, {%8,%9}, {%0,%1,%2,%3};"
                 : "+f"(d[0]), "+f"(d[1]), "+f"(d[2]), "+f"(d[3])
                 : "r"(a[0]), "r"(a[1]), "r"(a[2]), "r"(a[3]), "r"(b0), "r"(b1));
}
// D += A(16x16 f16) * B(16x8 f16)
__device__ __forceinline__ void mma16(float* d, uint32_t a0, uint32_t a1, uint32_t a2,
                                      uint32_t a3, uint32_t b0, uint32_t b1) {
    asm volatile("mma.sync.aligned.m16n8k16.row.col.f32.f16.f16.f32 "
                 "{%0,%1,%2,%3}, {%4,%5,%6,%7}, {%8,%9}, {%0,%1,%2,%3};"
                 : "+f"(d[0]), "+f"(d[1]), "+f"(d[2]), "+f"(d[3])
                 : "r"(a0), "r"(a1), "r"(a2), "r"(a3), "r"(b0), "r"(b1));
}

// S tile GEMM1 from padded pass1 layout
__device__ __forceinline__ void gemm1_tile(const __half* Qhs, int t,
                                           const uint32_t Ka[4][4], int g, int q,
                                           float* a0, float* a1) {
#pragma unroll
    for (int e = 0; e < 4; e++) { a0[e] = 0.f; a1[e] = 0.f; }
#pragma unroll
    for (int ks = 0; ks < 4; ks++) {
        uint2 q0 = *(const uint2*)&Qhs[(16 * t + g) * LDQH + 16 * ks + 4 * q];
        uint2 q1 = *(const uint2*)&Qhs[(16 * t + 8 + g) * LDQH + 16 * ks + 4 * q];
        mma16(a0, Ka[ks][0], Ka[ks][1], Ka[ks][2], Ka[ks][3], q0.x, q0.y);
        mma16(a1, Ka[ks][0], Ka[ks][1], Ka[ks][2], Ka[ks][3], q1.x, q1.y);
    }
}

// ---------------------------------------------------------------------------
// Kernel 1: projections via tf32 mma8. grid (16, 32), 256 thr (8 warps x 16 l).
// ---------------------------------------------------------------------------
#define KQ_XS   0
#define KQ_WS   (KQ_XS + 64*136)
#define KQ_STG  (KQ_WS + 176*72)
#define KQ_BIA  (KQ_STG + 128*72)
#define KQ_TOT  (KQ_BIA + 176)
#define LDX 136
#define LDW 72

__global__ __launch_bounds__(256) void kqv_mma(
        const float* __restrict__ x,
        const float* __restrict__ Wk, const float* __restrict__ bk,
        const float* __restrict__ Wq, const float* __restrict__ bq,
        const float* __restrict__ Wv, const float* __restrict__ bv,
        const void* __restrict__ slp) {
    extern __shared__ float sm[];
    float* xs   = sm + KQ_XS;
    float* Wsm  = sm + KQ_WS;
    float* stg  = sm + KQ_STG;
    float* bias = sm + KQ_BIA;

    const int tid = threadIdx.x;
    const int lane = tid & 31;
    const int wid = tid >> 5;
    const int g = lane >> 2, q = lane & 3;
    const int b = blockIdx.y;
    const int l0 = blockIdx.x * 128;
    const int r0 = wid * 16;
    const float kscale = rsqrtf(read_len(slp)) * 1.4426950408889634f;

    for (int idx = tid; idx < 56 * 64; idx += 256) {
        int d = idx >> 6, c = idx & 63;
        int pos = (c & ~7) | ((c & 3) << 1) | ((c >> 2) & 1);
        Wsm[d * LDW + pos]        = (d < DD) ? __uint_as_float(f2tf32(Wk[c * DD + d])) : 0.0f;
        Wsm[(56 + d) * LDW + pos] = (d < DD) ? __uint_as_float(f2tf32(Wq[c * DD + d])) : 0.0f;
    }
    for (int idx = tid; idx < 64 * 64; idx += 256) {
        int o = idx >> 6, c = idx & 63;
        int pos = (c & ~7) | ((c & 3) << 1) | ((c >> 2) & 1);
        Wsm[(112 + o) * LDW + pos] = __uint_as_float(f2tf32(Wv[c * CC + o]));
    }
    if (tid < 56)  bias[tid]       = (tid < DD) ? bk[tid] : 0.0f;
    if (tid < 56)  bias[56 + tid]  = (tid < DD) ? bq[tid] : 0.0f;
    if (tid < 64)  bias[112 + tid] = bv[tid];

    for (int idx = tid; idx < 64 * 32; idx += 256) {
        int row = idx >> 5, c4 = idx & 31;
        float4 v = *(const float4*)(x + (size_t)b * CC * LL + (size_t)row * LL + l0 + 4 * c4);
        v.x = __uint_as_float(f2tf32(v.x)); v.y = __uint_as_float(f2tf32(v.y));
        v.z = __uint_as_float(f2tf32(v.z)); v.w = __uint_as_float(f2tf32(v.w));
        *(float4*)&xs[row * LDX + 4 * c4] = v;
    }
    __syncthreads();

    uint32_t xa[8][4];
#pragma unroll
    for (int ks = 0; ks < 8; ks++) {
        xa[ks][0] = __float_as_uint(xs[(8 * ks + q) * LDX + r0 + g]);
        xa[ks][1] = __float_as_uint(xs[(8 * ks + q) * LDX + r0 + g + 8]);
        xa[ks][2] = __float_as_uint(xs[(8 * ks + q + 4) * LDX + r0 + g]);
        xa[ks][3] = __float_as_uint(xs[(8 * ks + q + 4) * LDX + r0 + g + 8]);
    }

    // ---- K ----
#pragma unroll
    for (int nt = 0; nt < 7; nt++) {
        float acc[4] = {0.f, 0.f, 0.f, 0.f};
#pragma unroll
        for (int ks = 0; ks < 8; ks++) {
            float2 bb = *(const float2*)&Wsm[(8 * nt + g) * LDW + 8 * ks + 2 * q];
            mma8(acc, xa[ks], __float_as_uint(bb.x), __float_as_uint(bb.y));
        }
        float b0 = bias[8 * nt + 2 * q], b1 = bias[8 * nt + 2 * q + 1];
        float v0 = acc[0] + b0, v1 = acc[1] + b1, v2 = acc[2] + b0, v3 = acc[3] + b1;
        v0 = (v0 > 0.f) ? v0 : expm1f(v0); v1 = (v1 > 0.f) ? v1 : expm1f(v1);
        v2 = (v2 > 0.f) ? v2 : expm1f(v2); v3 = (v3 > 0.f) ? v3 : expm1f(v3);
        *(float2*)&stg[(r0 + g) * LDW + 8 * nt + 2 * q]     = make_float2(v0, v1);
        *(float2*)&stg[(r0 + g + 8) * LDW + 8 * nt + 2 * q] = make_float2(v2, v3);
    }
    for (int idx = tid; idx < 128 * 8; idx += 256)
        stg[(idx >> 3) * LDW + 56 + (idx & 7)] = 0.0f;
    __syncthreads();
    for (int idx = tid; idx < 128 * 32; idx += 256) {
        int row = idx >> 5, p = (idx & 31) * 2;
        int pl = p & 15;
        int d0 = (p & ~15) + 2 * ((pl >> 2) & 3) + 8 * ((pl >> 1) & 1);
        __half2 h = __floats2half2_rn(stg[row * LDW + d0] * kscale,
                                      stg[row * LDW + d0 + 1] * kscale);
        *(__half2*)(g_Kh + ((size_t)b * LL + l0 + row) * DK + p) = h;
    }
    __syncthreads();

    // ---- Q ----
#pragma unroll
    for (int nt = 0; nt < 7; nt++) {
        float acc[4] = {0.f, 0.f, 0.f, 0.f};
#pragma unroll
        for (int ks = 0; ks < 8; ks++) {
            float2 bb = *(const float2*)&Wsm[(56 + 8 * nt + g) * LDW + 8 * ks + 2 * q];
            mma8(acc, xa[ks], __float_as_uint(bb.x), __float_as_uint(bb.y));
        }
        float b0 = bias[56 + 8 * nt + 2 * q], b1 = bias[56 + 8 * nt + 2 * q + 1];
        float v0 = acc[0] + b0, v1 = acc[1] + b1, v2 = acc[2] + b0, v3 = acc[3] + b1;
        v0 = (v0 > 0.f) ? v0 : expm1f(v0); v1 = (v1 > 0.f) ? v1 : expm1f(v1);
        v2 = (v2 > 0.f) ? v2 : expm1f(v2); v3 = (v3 > 0.f) ? v3 : expm1f(v3);
        *(float2*)&stg[(r0 + g) * LDW + 8 * nt + 2 * q]     = make_float2(v0, v1);
        *(float2*)&stg[(r0 + g + 8) * LDW + 8 * nt + 2 * q] = make_float2(v2, v3);
    }
    for (int idx = tid; idx < 128 * 8; idx += 256)
        stg[(idx >> 3) * LDW + 56 + (idx & 7)] = 0.0f;
    __syncthreads();
    for (int idx = tid; idx < 128 * 32; idx += 256) {
        int row = idx >> 5, p = (idx & 31) * 2;
        int pl = p & 15;
        int d0 = (p & ~15) + 2 * ((pl >> 2) & 3) + 8 * ((pl >> 1) & 1);
        __half2 h = __floats2half2_rn(stg[row * LDW + d0], stg[row * LDW + d0 + 1]);
        *(__half2*)(g_Qh + ((size_t)b * LL + l0 + row) * DK + p) = h;
    }
    __syncthreads();

    // ---- V ----
#pragma unroll
    for (int nt = 0; nt < 8; nt++) {
        float acc[4] = {0.f, 0.f, 0.f, 0.f};
#pragma unroll
        for (int ks = 0; ks < 8; ks++) {
            float2 bb = *(const float2*)&Wsm[(112 + 8 * nt + g) * LDW + 8 * ks + 2 * q];
            mma8(acc, xa[ks], __float_as_uint(bb.x), __float_as_uint(bb.y));
        }
        float b0 = bias[112 + 8 * nt + 2 * q], b1 = bias[112 + 8 * nt + 2 * q + 1];
        *(float2*)&stg[(r0 + g) * LDW + 8 * nt + 2 * q] =
            make_float2(tanhf(acc[0] + b0), tanhf(acc[1] + b1));
        *(float2*)&stg[(r0 + g + 8) * LDW + 8 * nt + 2 * q] =
            make_float2(tanhf(acc[2] + b0), tanhf(acc[3] + b1));
    }
    __syncthreads();
    for (int idx = tid; idx < 128 * 16; idx += 256) {
        int row = idx >> 4, c4 = idx & 15;
        *(float4*)(g_V + ((size_t)b * LL + l0 + row) * CC + 4 * c4) =
            *(float4*)&stg[row * LDW + 4 * c4];
    }
}

// ---------------------------------------------------------------------------
// Kernel 2 (pass1): S fp16 GEMM -> ex2.f16x2 -> column partials.
// Double-buffered Q staging via cp.async (prefetch mt+1 during compute of mt).
// grid (NLT, BB), 256 thr (8 warps x 16 l rows).
// ---------------------------------------------------------------------------
__global__ __launch_bounds__(256, 3) void pass1(void) {
    extern __shared__ char smraw[];
    const int QBUF = 128 * LDQH * 2;                 // 20480 B per buffer
    float* red = (float*)(smraw + 2 * QBUF);         // [8][128]

    const int tid = threadIdx.x;
    const int lane = tid & 31;
    const int wid = tid >> 5;
    const int g = lane >> 2, q = lane & 3;
    const int b = blockIdx.y;
    const int l0 = blockIdx.x * TL;
    const int r0 = wid * 16;
    const uint32_t sb = smem_u32(smraw);

    uint32_t Ka[4][4];
#pragma unroll
    for (int ks = 0; ks < 4; ks++) {
        uint2 lo = *(const uint2*)(g_Kh + ((size_t)b * LL + l0 + r0 + g) * DK + 16 * ks + 4 * q);
        uint2 hi = *(const uint2*)(g_Kh + ((size_t)b * LL + l0 + r0 + g + 8) * DK + 16 * ks + 4 * q);
        Ka[ks][0] = lo.x; Ka[ks][2] = lo.y;
        Ka[ks][1] = hi.x; Ka[ks][3] = hi.y;
    }

    // prologue prefetch of mt = 0
    for (int idx = tid; idx < 1024; idx += 256) {
        int row = idx >> 3, c8 = idx & 7;
        cpa16(sb + (uint32_t)(row * LDQH + 8 * c8) * 2,
              g_Qh + ((size_t)b * LL + row) * DK + 8 * c8);
    }
    CP_COMMIT();

    for (int mt = 0; mt < NMT; mt++) {
        CP_WAIT0();
        __syncthreads();
        if (mt < NMT - 1) {
            uint32_t qd = sb + ((mt + 1) & 1) * QBUF;
            const __half* src = g_Qh + ((size_t)b * LL + (mt + 1) * 128) * DK;
            for (int idx = tid; idx < 1024; idx += 256) {
                int row = idx >> 3, c8 = idx & 7;
                cpa16(qd + (uint32_t)(row * LDQH + 8 * c8) * 2,
                      src + (size_t)row * DK + 8 * c8);
            }
            CP_COMMIT();
        }
        const __half* Qhs = (const __half*)(smraw + (mt & 1) * QBUF);
        const int m0 = mt * 128;

        float a0[4], a1[4], n0[4], n1[4];
        gemm1_tile(Qhs, 0, Ka, g, q, a0, a1);

#pragma unroll
        for (int t = 0; t < 8; t++) {
            uint32_t px0 = ex2h2(packh2(a0[0], a0[1]));
            uint32_t px1 = ex2h2(packh2(a0[2], a0[3]));
            uint32_t py0 = ex2h2(packh2(a1[0], a1[1]));
            uint32_t py1 = ex2h2(packh2(a1[2], a1[3]));

            if (t < 7) gemm1_tile(Qhs, t + 1, Ka, g, q, n0, n1);

            __half2 h0 = __hadd2(*(__half2*)&px0, *(__half2*)&px1);
            __half2 h1 = __hadd2(*(__half2*)&py0, *(__half2*)&py1);
#pragma unroll
            for (int off = 4; off < 32; off <<= 1) {
                uint32_t u0 = __shfl_xor_sync(0xFFFFFFFFu, *(uint32_t*)&h0, off);
                uint32_t u1 = __shfl_xor_sync(0xFFFFFFFFu, *(uint32_t*)&h1, off);
                h0 = __hadd2(h0, *(__half2*)&u0);
                h1 = __hadd2(h1, *(__half2*)&u1);
            }
            if (lane < 4) {
                float2 f0 = __half22float2(h0);
                float2 f1 = __half22float2(h1);
                red[wid * 128 + 16 * t + 2 * q]         = f0.x;
                red[wid * 128 + 16 * t + 2 * q + 1]     = f0.y;
                red[wid * 128 + 16 * t + 8 + 2 * q]     = f1.x;
                red[wid * 128 + 16 * t + 8 + 2 * q + 1] = f1.y;
            }
#pragma unroll
            for (int e = 0; e < 4; e++) { a0[e] = n0[e]; a1[e] = n1[e]; }
        }
        __syncthreads();
        if (tid < 128) {
            float s = 0.f;
#pragma unroll
            for (int w = 0; w < 8; w++) s += red[w * 128 + tid];
            g_part[((size_t)blockIdx.x * BB + b) * LL + m0 + tid] = s;
        }
    }
}

// ---------------------------------------------------------------------------
// Kernel 3: cinv; V' = fp16(V*cinv) transposed [c][m'] perm16.
// ---------------------------------------------------------------------------
__global__ void prep_kernel() {
    __shared__ float ci[64];
    __shared__ float vt[64 * 68];
    const int tid = threadIdx.x;
    const int b = blockIdx.y;
    const int m0 = blockIdx.x * 64;

    if (tid < 64) {
        float s = 0.0f;
#pragma unroll
        for (int lt = 0; lt < NLT; lt++)
            s += g_part[((size_t)lt * BB + b) * LL + m0 + tid];
        ci[tid] = 1.0f / s;
    }
    for (int idx = tid; idx < 64 * 16; idx += 256) {
        int row = idx >> 4, c4 = idx & 15;
        *(float4*)&vt[row * 68 + 4 * c4] =
            *(const float4*)(g_V + ((size_t)b * LL + m0 + row) * CC + 4 * c4);
    }
    __syncthreads();
    for (int idx = tid; idx < 64 * 32; idx += 256) {
        int c = idx >> 5, jp = idx & 31;
        int m = 16 * (jp >> 3) + 8 * (jp & 1) + 2 * ((jp >> 1) & 3);
        __half2 hv = __floats2half2_rn(vt[m * 68 + c] * ci[m],
                                       vt[(m + 1) * 68 + c] * ci[m + 1]);
        *(__half2*)(g_Vph + ((size_t)b * CC + c) * LL + m0 + 2 * jp) = hv;
    }
}

// ---------------------------------------------------------------------------
// Kernel 4 (pass2): fused S GEMM -> exp -> Y GEMM, R11 structure (4 warps x
// 32 rows, 2x B-frag reuse), with XOR-swizzled packed tiles (Q 16KB, V' 16KB)
// double-buffered via cp.async. grid (NLT, BB), 128 thr.
// Q layout: halves = row*64 + 16*(ks ^ (row&3)) + in-chunk(0..15)
// V' layout: halves = row*128 + 16*(t ^ (row&3)) + in-chunk(0..15)
// ---------------------------------------------------------------------------
#define P2_Q0 0
#define P2_Q1 16384
#define P2_V0 32768
#define P2_V1 49152
#define P2_TOT 65536

__global__ __launch_bounds__(128, 3) void pass2(float* __restrict__ out) {
    extern __shared__ char smraw[];
    const uint32_t sb = smem_u32(smraw);

    const int tid = threadIdx.x;
    const int lane = tid & 31;
    const int wid = tid >> 5;
    const int g = lane >> 2, q = lane & 3;
    const int b = blockIdx.y;
    const int l0 = blockIdx.x * TL;
    const int r0 = wid * 32;

    uint32_t Ka0[4][4], Ka1[4][4];
#pragma unroll
    for (int ks = 0; ks < 4; ks++) {
        uint2 lo = *(const uint2*)(g_Kh + ((size_t)b * LL + l0 + r0 + g) * DK + 16 * ks + 4 * q);
        uint2 hi = *(const uint2*)(g_Kh + ((size_t)b * LL + l0 + r0 + g + 8) * DK + 16 * ks + 4 * q);
        Ka0[ks][0] = lo.x; Ka0[ks][2] = lo.y;
        Ka0[ks][1] = hi.x; Ka0[ks][3] = hi.y;
        uint2 lo1 = *(const uint2*)(g_Kh + ((size_t)b * LL + l0 + r0 + 16 + g) * DK + 16 * ks + 4 * q);
        uint2 hi1 = *(const uint2*)(g_Kh + ((size_t)b * LL + l0 + r0 + 24 + g) * DK + 16 * ks + 4 * q);
        Ka1[ks][0] = lo1.x; Ka1[ks][2] = lo1.y;
        Ka1[ks][1] = hi1.x; Ka1[ks][3] = hi1.y;
    }

    float y0[8][4], y1[8][4];
#pragma unroll
    for (int n = 0; n < 8; n++)
#pragma unroll
        for (int e = 0; e < 4; e++) { y0[n][e] = 0.f; y1[n][e] = 0.f; }

    // stage helper (as macro-ish lambda): Q 1024 chunks, V' 1024 chunks
#define P2_STAGE(qbase, vbase, m0_)                                                 \
    do {                                                                            \
        const __half* qsrc = g_Qh + ((size_t)b * LL + (m0_)) * DK;                  \
        for (int idx = tid; idx < 1024; idx += 128) {                               \
            int row = idx >> 3, c8 = idx & 7;                                       \
            uint32_t d = (qbase) + (uint32_t)(row * 128 +                           \
                          32 * (((c8 >> 1) ^ (row & 3))) + 16 * (c8 & 1));          \
            cpa16(d, qsrc + (size_t)row * DK + 8 * c8);                             \
        }                                                                           \
        const __half* vsrc = g_Vph + (size_t)b * CC * LL + (m0_);                   \
        for (int idx = tid; idx < 1024; idx += 128) {                               \
            int row = idx >> 4, c8 = idx & 15;                                      \
            uint32_t d = (vbase) + (uint32_t)(row * 256 +                           \
                          32 * (((c8 >> 1) ^ (row & 3))) + 16 * (c8 & 1));          \
            cpa16(d, vsrc + (size_t)row * LL + 8 * c8);                             \
        }                                                                           \
    } while (0)

    P2_STAGE(sb + P2_Q0, sb + P2_V0, 0);
    CP_COMMIT();

    for (int mt = 0; mt < NMT; mt++) {
        CP_WAIT0();
        __syncthreads();
        if (mt < NMT - 1) {
            uint32_t qb = sb + (((mt + 1) & 1) ? P2_Q1 : P2_Q0);
            uint32_t vb = sb + (((mt + 1) & 1) ? P2_V1 : P2_V0);
            P2_STAGE(qb, vb, (mt + 1) * 128);
            CP_COMMIT();
        }
        const __half* Qc = (const __half*)(smraw + ((mt & 1) ? P2_Q1 : P2_Q0));
        const __half* Vc = (const __half*)(smraw + ((mt & 1) ? P2_V1 : P2_V0));

#pragma unroll
        for (int t = 0; t < 8; t++) {
            // GEMM1 for both row-groups; B-frags (Q) loaded once, swizzled
            float a0A[4] = {0.f,0.f,0.f,0.f}, a1A[4] = {0.f,0.f,0.f,0.f};
            float a0B[4] = {0.f,0.f,0.f,0.f}, a1B[4] = {0.f,0.f,0.f,0.f};
#pragma unroll
            for (int ks = 0; ks < 4; ks++) {
                int co = 16 * (ks ^ (g & 3)) + 4 * q;
                uint2 q0 = *(const uint2*)&Qc[(16 * t + g) * 64 + co];
                uint2 q1 = *(const uint2*)&Qc[(16 * t + 8 + g) * 64 + co];
                mma16(a0A, Ka0[ks][0], Ka0[ks][1], Ka0[ks][2], Ka0[ks][3], q0.x, q0.y);
                mma16(a1A, Ka0[ks][0], Ka0[ks][1], Ka0[ks][2], Ka0[ks][3], q1.x, q1.y);
                mma16(a0B, Ka1[ks][0], Ka1[ks][1], Ka1[ks][2], Ka1[ks][3], q0.x, q0.y);
                mma16(a1B, Ka1[ks][0], Ka1[ks][1], Ka1[ks][2], Ka1[ks][3], q1.x, q1.y);
            }
            // exp -> fp16 A fragments (layout identity)
            uint32_t pxA0 = ex2h2(packh2(a0A[0], a0A[1]));
            uint32_t pxA1 = ex2h2(packh2(a0A[2], a0A[3]));
            uint32_t pyA0 = ex2h2(packh2(a1A[0], a1A[1]));
            uint32_t pyA1 = ex2h2(packh2(a1A[2], a1A[3]));
            uint32_t pxB0 = ex2h2(packh2(a0B[0], a0B[1]));
            uint32_t pxB1 = ex2h2(packh2(a0B[2], a0B[3]));
            uint32_t pyB0 = ex2h2(packh2(a1B[0], a1B[1]));
            uint32_t pyB1 = ex2h2(packh2(a1B[2], a1B[3]));

            // GEMM2 for both row-groups; B-frags (V') loaded once, swizzled
#pragma unroll
            for (int n = 0; n < 8; n++) {
                uint2 bb = *(const uint2*)&Vc[(8 * n + g) * 128 + 16 * (t ^ (g & 3)) + 4 * q];
                mma16(y0[n], pxA0, pxA1, pyA0, pyA1, bb.x, bb.y);
                mma16(y1[n], pxB0, pxB1, pyB0, pyB1, bb.x, bb.y);
            }
        }
    }

    float* ob0 = out + ((size_t)b * LL + l0 + r0) * CC;
    float* ob1 = out + ((size_t)b * LL + l0 + r0 + 16) * CC;
#pragma unroll
    for (int n = 0; n < 8; n++) {
        *(float2*)&ob0[(size_t)g * CC + 8 * n + 2 * q]       = make_float2(y0[n][0], y0[n][1]);
        *(float2*)&ob0[(size_t)(g + 8) * CC + 8 * n + 2 * q] = make_float2(y0[n][2], y0[n][3]);
        *(float2*)&ob1[(size_t)g * CC + 8 * n + 2 * q]       = make_float2(y1[n][0], y1[n][1]);
        *(float2*)&ob1[(size_t)(g + 8) * CC + 8 * n + 2 * q] = make_float2(y1[n][2], y1[n][3]);
    }
}

// ---------------------------------------------------------------------------
extern "C" void kernel_launch(void* const* d_in, const int* in_sizes, int n_in,
                              void* d_out, int out_size) {
    const float* x  = (const float*)d_in[0];
    const float* Wk = (const float*)d_in[1];
    const float* bk = (const float*)d_in[2];
    const float* Wq = (const float*)d_in[3];
    const float* bq = (const float*)d_in[4];
    const float* Wv = (const float*)d_in[5];
    const float* bv = (const float*)d_in[6];
    const void*  sl = (const void*)d_in[7];
    float* out = (float*)d_out;

    const int kq_smem = KQ_TOT * (int)sizeof(float);
    const int p1_smem = 2 * 128 * LDQH * 2 + 8 * 128 * (int)sizeof(float);
    const int p2_smem = P2_TOT;

    static bool attr_set = false;
    if (!attr_set) {
        cudaFuncSetAttribute(kqv_mma, cudaFuncAttributeMaxDynamicSharedMemorySize, kq_smem);
        cudaFuncSetAttribute(pass1,   cudaFuncAttributeMaxDynamicSharedMemorySize, p1_smem);
        cudaFuncSetAttribute(pass2,   cudaFuncAttributeMaxDynamicSharedMemorySize, p2_smem);
        attr_set = true;
    }

    dim3 g1(NLT, BB);
    kqv_mma<<<g1, 256, kq_smem>>>(x, Wk, bk, Wq, bq, Wv, bv, sl);

    dim3 g2(NLT, BB);
    pass1<<<g2, 256, p1_smem>>>();

    dim3 g3(LL / 64, BB);
    prep_kernel<<<g3, 256>>>();

    dim3 g4(NLT, BB);
    pass2<<<g4, 128, p2_smem>>>(out);
}

// round 15
// speedup vs baseline: 1.9376x; 1.1490x over previous
#include <cuda_runtime.h>
#include <cuda_fp16.h>
#include <math.h>
#include <stdint.h>

// Problem constants
#define BB 32
#define CC 64
#define LL 2048
#define DD 50
#define DK 64
#define TL 128
#define NLT (LL/TL)    // 16
#define NMT (LL/128)   // 16

// Scratch (device globals — allocation is forbidden)
// g_Kh/g_Qh: fp16, d interleaved within 16-chunks: pos 4q..4q+3 hold d = 2q,2q+1,2q+8,2q+9.
// g_Kh pre-scaled by log2e/sqrt(sample_len).
__device__ __half g_Kh[BB*LL*DK];
__device__ __half g_Qh[BB*LL*DK];
__device__ float  g_V[BB*LL*CC];          // tanh(xWv+bv), [m][c] fp32
__device__ __half g_Vph[BB*CC*LL];        // V' = V*cinv, [c][m'] perm16 on m
__device__ float  g_part[NLT*BB*LL];      // per-ltile column partials

#define LDQH 80        // pass1 smem leading dim (halves); 40 words -> conflict-free

__device__ __forceinline__ float read_len(const void* p) {
    int i = *(const int*)p;
    if (i > 0 && i < (1 << 24)) return (float)i;
    return __int_as_float(i);
}
__device__ __forceinline__ uint32_t smem_u32(const void* p) {
    uint32_t a;
    asm("{ .reg .u64 t; cvta.to.shared.u64 t, %1; cvt.u32.u64 %0, t; }" : "=r"(a) : "l"(p));
    return a;
}
__device__ __forceinline__ void cpa16(uint32_t dst, const void* src) {
    asm volatile("cp.async.cg.shared.global [%0], [%1], 16;" :: "r"(dst), "l"(src));
}
#define CP_COMMIT() asm volatile("cp.async.commit_group;" ::: "memory")
#define CP_WAIT0()  asm volatile("cp.async.wait_group 0;" ::: "memory")

__device__ __forceinline__ uint32_t f2tf32(float x) {
    uint32_t u;
    asm("cvt.rna.tf32.f32 %0, %1;" : "=r"(u) : "f"(x));
    return u;
}
__device__ __forceinline__ uint32_t packh2(float lo, float hi) {
    __half2 h = __floats2half2_rn(lo, hi);
    return *(uint32_t*)&h;
}
__device__ __forceinline__ uint32_t ex2h2(uint32_t v) {
    uint32_t r;
    asm("ex2.approx.f16x2 %0, %1;" : "=r"(r) : "r"(v));
    return r;
}
// D += A(16x8 tf32) * B(8x8 tf32)
__device__ __forceinline__ void mma8(float* d, const uint32_t* a, uint32_t b0, uint32_t b1) {
    asm volatile("mma.sync.aligned.m16n8k8.row.col.f32.tf32.tf32.f32 "
                 "{%0,%1,%2,%3}, {%4,%5,%6,%7}, {%8,%9}, {%0,%1,%2,%3};"
                 : "+f"(d[0]), "+f"(d[1]), "+f"(d[2]), "+f"(d[3])
                 : "r"(a[0]), "r"(a[1]), "r"(a[2]), "r"(a[3]), "r"(b0), "r"(b1));
}
// D += A(16x16 f16) * B(16x8 f16)
__device__ __forceinline__ void mma16(float* d, uint32_t a0, uint32_t a1, uint32_t a2,
                                      uint32_t a3, uint32_t b0, uint32_t b1) {
    asm volatile("mma.sync.aligned.m16n8k16.row.col.f32.f16.f16.f32 "
                 "{%0,%1,%2,%3}, {%4,%5,%6,%7}, {%8,%9}, {%0,%1,%2,%3};"
                 : "+f"(d[0]), "+f"(d[1]), "+f"(d[2]), "+f"(d[3])
                 : "r"(a0), "r"(a1), "r"(a2), "r"(a3), "r"(b0), "r"(b1));
}

// ---------------------------------------------------------------------------
// Kernel 1: projections via tf32 mma8. grid (16, 32), 256 thr (8 warps x 16 l).
// Staging buffer ALIASES the x tile (dead after xa fragments are cached) ->
// smem 86KB -> 2 CTAs/SM.
// ---------------------------------------------------------------------------
#define LDX 136
#define LDW 72         // Wsm leading dim
#define LDS_T 68       // staging leading dim (128*68 == 64*136 exactly)
#define KQ_XS   0
#define KQ_WS   (64*136)
#define KQ_BIA  (KQ_WS + 176*LDW)
#define KQ_TOT  (KQ_BIA + 176)

__global__ __launch_bounds__(256, 2) void kqv_mma(
        const float* __restrict__ x,
        const float* __restrict__ Wk, const float* __restrict__ bk,
        const float* __restrict__ Wq, const float* __restrict__ bq,
        const float* __restrict__ Wv, const float* __restrict__ bv,
        const void* __restrict__ slp) {
    extern __shared__ float sm[];
    float* xs   = sm + KQ_XS;     // [64][136]
    float* stg  = sm + KQ_XS;     // [128][68] — aliases xs (dead after xa load)
    float* Wsm  = sm + KQ_WS;
    float* bias = sm + KQ_BIA;

    const int tid = threadIdx.x;
    const int lane = tid & 31;
    const int wid = tid >> 5;
    const int g = lane >> 2, q = lane & 3;
    const int b = blockIdx.y;
    const int l0 = blockIdx.x * 128;
    const int r0 = wid * 16;
    const float kscale = rsqrtf(read_len(slp)) * 1.4426950408889634f;

    for (int idx = tid; idx < 56 * 64; idx += 256) {
        int d = idx >> 6, c = idx & 63;
        int pos = (c & ~7) | ((c & 3) << 1) | ((c >> 2) & 1);
        Wsm[d * LDW + pos]        = (d < DD) ? __uint_as_float(f2tf32(Wk[c * DD + d])) : 0.0f;
        Wsm[(56 + d) * LDW + pos] = (d < DD) ? __uint_as_float(f2tf32(Wq[c * DD + d])) : 0.0f;
    }
    for (int idx = tid; idx < 64 * 64; idx += 256) {
        int o = idx >> 6, c = idx & 63;
        int pos = (c & ~7) | ((c & 3) << 1) | ((c >> 2) & 1);
        Wsm[(112 + o) * LDW + pos] = __uint_as_float(f2tf32(Wv[c * CC + o]));
    }
    if (tid < 56)  bias[tid]       = (tid < DD) ? bk[tid] : 0.0f;
    if (tid < 56)  bias[56 + tid]  = (tid < DD) ? bq[tid] : 0.0f;
    if (tid < 64)  bias[112 + tid] = bv[tid];

    for (int idx = tid; idx < 64 * 32; idx += 256) {
        int row = idx >> 5, c4 = idx & 31;
        float4 v = *(const float4*)(x + (size_t)b * CC * LL + (size_t)row * LL + l0 + 4 * c4);
        v.x = __uint_as_float(f2tf32(v.x)); v.y = __uint_as_float(f2tf32(v.y));
        v.z = __uint_as_float(f2tf32(v.z)); v.w = __uint_as_float(f2tf32(v.w));
        *(float4*)&xs[row * LDX + 4 * c4] = v;
    }
    __syncthreads();

    uint32_t xa[8][4];
#pragma unroll
    for (int ks = 0; ks < 8; ks++) {
        xa[ks][0] = __float_as_uint(xs[(8 * ks + q) * LDX + r0 + g]);
        xa[ks][1] = __float_as_uint(xs[(8 * ks + q) * LDX + r0 + g + 8]);
        xa[ks][2] = __float_as_uint(xs[(8 * ks + q + 4) * LDX + r0 + g]);
        xa[ks][3] = __float_as_uint(xs[(8 * ks + q + 4) * LDX + r0 + g + 8]);
    }
    __syncthreads();   // xs now dead; stg may overwrite it

    // ---- K ----
#pragma unroll
    for (int nt = 0; nt < 7; nt++) {
        float acc[4] = {0.f, 0.f, 0.f, 0.f};
#pragma unroll
        for (int ks = 0; ks < 8; ks++) {
            float2 bb = *(const float2*)&Wsm[(8 * nt + g) * LDW + 8 * ks + 2 * q];
            mma8(acc, xa[ks], __float_as_uint(bb.x), __float_as_uint(bb.y));
        }
        float b0 = bias[8 * nt + 2 * q], b1 = bias[8 * nt + 2 * q + 1];
        float v0 = acc[0] + b0, v1 = acc[1] + b1, v2 = acc[2] + b0, v3 = acc[3] + b1;
        v0 = (v0 > 0.f) ? v0 : expm1f(v0); v1 = (v1 > 0.f) ? v1 : expm1f(v1);
        v2 = (v2 > 0.f) ? v2 : expm1f(v2); v3 = (v3 > 0.f) ? v3 : expm1f(v3);
        *(float2*)&stg[(r0 + g) * LDS_T + 8 * nt + 2 * q]     = make_float2(v0, v1);
        *(float2*)&stg[(r0 + g + 8) * LDS_T + 8 * nt + 2 * q] = make_float2(v2, v3);
    }
    for (int idx = tid; idx < 128 * 8; idx += 256)
        stg[(idx >> 3) * LDS_T + 56 + (idx & 7)] = 0.0f;
    __syncthreads();
    for (int idx = tid; idx < 128 * 32; idx += 256) {
        int row = idx >> 5, p = (idx & 31) * 2;
        int pl = p & 15;
        int d0 = (p & ~15) + 2 * ((pl >> 2) & 3) + 8 * ((pl >> 1) & 1);
        __half2 h = __floats2half2_rn(stg[row * LDS_T + d0] * kscale,
                                      stg[row * LDS_T + d0 + 1] * kscale);
        *(__half2*)(g_Kh + ((size_t)b * LL + l0 + row) * DK + p) = h;
    }
    __syncthreads();

    // ---- Q ----
#pragma unroll
    for (int nt = 0; nt < 7; nt++) {
        float acc[4] = {0.f, 0.f, 0.f, 0.f};
#pragma unroll
        for (int ks = 0; ks < 8; ks++) {
            float2 bb = *(const float2*)&Wsm[(56 + 8 * nt + g) * LDW + 8 * ks + 2 * q];
            mma8(acc, xa[ks], __float_as_uint(bb.x), __float_as_uint(bb.y));
        }
        float b0 = bias[56 + 8 * nt + 2 * q], b1 = bias[56 + 8 * nt + 2 * q + 1];
        float v0 = acc[0] + b0, v1 = acc[1] + b1, v2 = acc[2] + b0, v3 = acc[3] + b1;
        v0 = (v0 > 0.f) ? v0 : expm1f(v0); v1 = (v1 > 0.f) ? v1 : expm1f(v1);
        v2 = (v2 > 0.f) ? v2 : expm1f(v2); v3 = (v3 > 0.f) ? v3 : expm1f(v3);
        *(float2*)&stg[(r0 + g) * LDS_T + 8 * nt + 2 * q]     = make_float2(v0, v1);
        *(float2*)&stg[(r0 + g + 8) * LDS_T + 8 * nt + 2 * q] = make_float2(v2, v3);
    }
    for (int idx = tid; idx < 128 * 8; idx += 256)
        stg[(idx >> 3) * LDS_T + 56 + (idx & 7)] = 0.0f;
    __syncthreads();
    for (int idx = tid; idx < 128 * 32; idx += 256) {
        int row = idx >> 5, p = (idx & 31) * 2;
        int pl = p & 15;
        int d0 = (p & ~15) + 2 * ((pl >> 2) & 3) + 8 * ((pl >> 1) & 1);
        __half2 h = __floats2half2_rn(stg[row * LDS_T + d0], stg[row * LDS_T + d0 + 1]);
        *(__half2*)(g_Qh + ((size_t)b * LL + l0 + row) * DK + p) = h;
    }
    __syncthreads();

    // ---- V ----
#pragma unroll
    for (int nt = 0; nt < 8; nt++) {
        float acc[4] = {0.f, 0.f, 0.f, 0.f};
#pragma unroll
        for (int ks = 0; ks < 8; ks++) {
            float2 bb = *(const float2*)&Wsm[(112 + 8 * nt + g) * LDW + 8 * ks + 2 * q];
            mma8(acc, xa[ks], __float_as_uint(bb.x), __float_as_uint(bb.y));
        }
        float b0 = bias[112 + 8 * nt + 2 * q], b1 = bias[112 + 8 * nt + 2 * q + 1];
        *(float2*)&stg[(r0 + g) * LDS_T + 8 * nt + 2 * q] =
            make_float2(tanhf(acc[0] + b0), tanhf(acc[1] + b1));
        *(float2*)&stg[(r0 + g + 8) * LDS_T + 8 * nt + 2 * q] =
            make_float2(tanhf(acc[2] + b0), tanhf(acc[3] + b1));
    }
    __syncthreads();
    for (int idx = tid; idx < 128 * 16; idx += 256) {
        int row = idx >> 4, c4 = idx & 15;
        *(float4*)(g_V + ((size_t)b * LL + l0 + row) * CC + 4 * c4) =
            *(float4*)&stg[row * LDS_T + 4 * c4];
    }
}

// ---------------------------------------------------------------------------
// Kernel 2 (pass1): S fp16 GEMM -> ex2.f16x2 -> column partials.
// 4 warps x 32 rows (2x B-frag reuse), cp.async double-buffered Q.
// grid (NLT, BB), 128 thr.
// ---------------------------------------------------------------------------
__global__ __launch_bounds__(128, 5) void pass1(void) {
    extern __shared__ char smraw[];
    const int QBUF = 128 * LDQH * 2;                 // 20480 B per buffer
    float* red = (float*)(smraw + 2 * QBUF);         // [4][128]

    const int tid = threadIdx.x;
    const int lane = tid & 31;
    const int wid = tid >> 5;          // 0..3
    const int g = lane >> 2, q = lane & 3;
    const int b = blockIdx.y;
    const int l0 = blockIdx.x * TL;
    const int r0 = wid * 32;
    const uint32_t sb = smem_u32(smraw);

    uint32_t Ka0[4][4], Ka1[4][4];
#pragma unroll
    for (int ks = 0; ks < 4; ks++) {
        uint2 lo = *(const uint2*)(g_Kh + ((size_t)b * LL + l0 + r0 + g) * DK + 16 * ks + 4 * q);
        uint2 hi = *(const uint2*)(g_Kh + ((size_t)b * LL + l0 + r0 + g + 8) * DK + 16 * ks + 4 * q);
        Ka0[ks][0] = lo.x; Ka0[ks][2] = lo.y;
        Ka0[ks][1] = hi.x; Ka0[ks][3] = hi.y;
        uint2 lo1 = *(const uint2*)(g_Kh + ((size_t)b * LL + l0 + r0 + 16 + g) * DK + 16 * ks + 4 * q);
        uint2 hi1 = *(const uint2*)(g_Kh + ((size_t)b * LL + l0 + r0 + 24 + g) * DK + 16 * ks + 4 * q);
        Ka1[ks][0] = lo1.x; Ka1[ks][2] = lo1.y;
        Ka1[ks][1] = hi1.x; Ka1[ks][3] = hi1.y;
    }

    // prologue prefetch of mt = 0
    for (int idx = tid; idx < 1024; idx += 128) {
        int row = idx >> 3, c8 = idx & 7;
        cpa16(sb + (uint32_t)(row * LDQH + 8 * c8) * 2,
              g_Qh + ((size_t)b * LL + row) * DK + 8 * c8);
    }
    CP_COMMIT();

    for (int mt = 0; mt < NMT; mt++) {
        CP_WAIT0();
        __syncthreads();
        if (mt < NMT - 1) {
            uint32_t qd = sb + ((mt + 1) & 1) * QBUF;
            const __half* src = g_Qh + ((size_t)b * LL + (mt + 1) * 128) * DK;
            for (int idx = tid; idx < 1024; idx += 128) {
                int row = idx >> 3, c8 = idx & 7;
                cpa16(qd + (uint32_t)(row * LDQH + 8 * c8) * 2,
                      src + (size_t)row * DK + 8 * c8);
            }
            CP_COMMIT();
        }
        const __half* Qhs = (const __half*)(smraw + (mt & 1) * QBUF);
        const int m0 = mt * 128;

#pragma unroll
        for (int t = 0; t < 8; t++) {
            float a0A[4] = {0.f,0.f,0.f,0.f}, a1A[4] = {0.f,0.f,0.f,0.f};
            float a0B[4] = {0.f,0.f,0.f,0.f}, a1B[4] = {0.f,0.f,0.f,0.f};
#pragma unroll
            for (int ks = 0; ks < 4; ks++) {
                uint2 q0 = *(const uint2*)&Qhs[(16 * t + g) * LDQH + 16 * ks + 4 * q];
                uint2 q1 = *(const uint2*)&Qhs[(16 * t + 8 + g) * LDQH + 16 * ks + 4 * q];
                mma16(a0A, Ka0[ks][0], Ka0[ks][1], Ka0[ks][2], Ka0[ks][3], q0.x, q0.y);
                mma16(a1A, Ka0[ks][0], Ka0[ks][1], Ka0[ks][2], Ka0[ks][3], q1.x, q1.y);
                mma16(a0B, Ka1[ks][0], Ka1[ks][1], Ka1[ks][2], Ka1[ks][3], q0.x, q0.y);
                mma16(a1B, Ka1[ks][0], Ka1[ks][1], Ka1[ks][2], Ka1[ks][3], q1.x, q1.y);
            }
            uint32_t pxA0 = ex2h2(packh2(a0A[0], a0A[1]));
            uint32_t pxA1 = ex2h2(packh2(a0A[2], a0A[3]));
            uint32_t pyA0 = ex2h2(packh2(a1A[0], a1A[1]));
            uint32_t pyA1 = ex2h2(packh2(a1A[2], a1A[3]));
            uint32_t pxB0 = ex2h2(packh2(a0B[0], a0B[1]));
            uint32_t pxB1 = ex2h2(packh2(a0B[2], a0B[3]));
            uint32_t pyB0 = ex2h2(packh2(a1B[0], a1B[1]));
            uint32_t pyB1 = ex2h2(packh2(a1B[2], a1B[3]));

            // column partials over the warp's 32 rows
            __half2 h0 = __hadd2(__hadd2(*(__half2*)&pxA0, *(__half2*)&pxA1),
                                 __hadd2(*(__half2*)&pxB0, *(__half2*)&pxB1));
            __half2 h1 = __hadd2(__hadd2(*(__half2*)&pyA0, *(__half2*)&pyA1),
                                 __hadd2(*(__half2*)&pyB0, *(__half2*)&pyB1));
#pragma unroll
            for (int off = 4; off < 32; off <<= 1) {
                uint32_t u0 = __shfl_xor_sync(0xFFFFFFFFu, *(uint32_t*)&h0, off);
                uint32_t u1 = __shfl_xor_sync(0xFFFFFFFFu, *(uint32_t*)&h1, off);
                h0 = __hadd2(h0, *(__half2*)&u0);
                h1 = __hadd2(h1, *(__half2*)&u1);
            }
            if (lane < 4) {
                float2 f0 = __half22float2(h0);
                float2 f1 = __half22float2(h1);
                red[wid * 128 + 16 * t + 2 * q]         = f0.x;
                red[wid * 128 + 16 * t + 2 * q + 1]     = f0.y;
                red[wid * 128 + 16 * t + 8 + 2 * q]     = f1.x;
                red[wid * 128 + 16 * t + 8 + 2 * q + 1] = f1.y;
            }
        }
        __syncthreads();
        {
            float s = red[tid] + red[128 + tid] + red[256 + tid] + red[384 + tid];
            g_part[((size_t)blockIdx.x * BB + b) * LL + m0 + tid] = s;
        }
    }
}

// ---------------------------------------------------------------------------
// Kernel 3: cinv; V' = fp16(V*cinv) transposed [c][m'] perm16.
// ---------------------------------------------------------------------------
__global__ void prep_kernel() {
    __shared__ float ci[64];
    __shared__ float vt[64 * 68];
    const int tid = threadIdx.x;
    const int b = blockIdx.y;
    const int m0 = blockIdx.x * 64;

    if (tid < 64) {
        float s = 0.0f;
#pragma unroll
        for (int lt = 0; lt < NLT; lt++)
            s += g_part[((size_t)lt * BB + b) * LL + m0 + tid];
        ci[tid] = 1.0f / s;
    }
    for (int idx = tid; idx < 64 * 16; idx += 256) {
        int row = idx >> 4, c4 = idx & 15;
        *(float4*)&vt[row * 68 + 4 * c4] =
            *(const float4*)(g_V + ((size_t)b * LL + m0 + row) * CC + 4 * c4);
    }
    __syncthreads();
    for (int idx = tid; idx < 64 * 32; idx += 256) {
        int c = idx >> 5, jp = idx & 31;
        int m = 16 * (jp >> 3) + 8 * (jp & 1) + 2 * ((jp >> 1) & 3);
        __half2 hv = __floats2half2_rn(vt[m * 68 + c] * ci[m],
                                       vt[(m + 1) * 68 + c] * ci[m + 1]);
        *(__half2*)(g_Vph + ((size_t)b * CC + c) * LL + m0 + 2 * jp) = hv;
    }
}

// ---------------------------------------------------------------------------
// Kernel 4 (pass2): fused S GEMM -> exp -> Y GEMM, R14 version (unchanged):
// 4 warps x 32 rows, 2x B-frag reuse, XOR-swizzled packed tiles, cp.async
// double-buffered. grid (NLT, BB), 128 thr.
// ---------------------------------------------------------------------------
#define P2_Q0 0
#define P2_Q1 16384
#define P2_V0 32768
#define P2_V1 49152
#define P2_TOT 65536

__global__ __launch_bounds__(128, 3) void pass2(float* __restrict__ out) {
    extern __shared__ char smraw[];
    const uint32_t sb = smem_u32(smraw);

    const int tid = threadIdx.x;
    const int lane = tid & 31;
    const int wid = tid >> 5;
    const int g = lane >> 2, q = lane & 3;
    const int b = blockIdx.y;
    const int l0 = blockIdx.x * TL;
    const int r0 = wid * 32;

    uint32_t Ka0[4][4], Ka1[4][4];
#pragma unroll
    for (int ks = 0; ks < 4; ks++) {
        uint2 lo = *(const uint2*)(g_Kh + ((size_t)b * LL + l0 + r0 + g) * DK + 16 * ks + 4 * q);
        uint2 hi = *(const uint2*)(g_Kh + ((size_t)b * LL + l0 + r0 + g + 8) * DK + 16 * ks + 4 * q);
        Ka0[ks][0] = lo.x; Ka0[ks][2] = lo.y;
        Ka0[ks][1] = hi.x; Ka0[ks][3] = hi.y;
        uint2 lo1 = *(const uint2*)(g_Kh + ((size_t)b * LL + l0 + r0 + 16 + g) * DK + 16 * ks + 4 * q);
        uint2 hi1 = *(const uint2*)(g_Kh + ((size_t)b * LL + l0 + r0 + 24 + g) * DK + 16 * ks + 4 * q);
        Ka1[ks][0] = lo1.x; Ka1[ks][2] = lo1.y;
        Ka1[ks][1] = hi1.x; Ka1[ks][3] = hi1.y;
    }

    float y0[8][4], y1[8][4];
#pragma unroll
    for (int n = 0; n < 8; n++)
#pragma unroll
        for (int e = 0; e < 4; e++) { y0[n][e] = 0.f; y1[n][e] = 0.f; }

#define P2_STAGE(qbase, vbase, m0_)                                                 \
    do {                                                                            \
        const __half* qsrc = g_Qh + ((size_t)b * LL + (m0_)) * DK;                  \
        for (int idx = tid; idx < 1024; idx += 128) {                               \
            int row = idx >> 3, c8 = idx & 7;                                       \
            uint32_t d = (qbase) + (uint32_t)(row * 128 +                           \
                          32 * (((c8 >> 1) ^ (row & 3))) + 16 * (c8 & 1));          \
            cpa16(d, qsrc + (size_t)row * DK + 8 * c8);                             \
        }                                                                           \
        const __half* vsrc = g_Vph + (size_t)b * CC * LL + (m0_);                   \
        for (int idx = tid; idx < 1024; idx += 128) {                               \
            int row = idx >> 4, c8 = idx & 15;                                      \
            uint32_t d = (vbase) + (uint32_t)(row * 256 +                           \
                          32 * (((c8 >> 1) ^ (row & 3))) + 16 * (c8 & 1));          \
            cpa16(d, vsrc + (size_t)row * LL + 8 * c8);                             \
        }                                                                           \
    } while (0)

    P2_STAGE(sb + P2_Q0, sb + P2_V0, 0);
    CP_COMMIT();

    for (int mt = 0; mt < NMT; mt++) {
        CP_WAIT0();
        __syncthreads();
        if (mt < NMT - 1) {
            uint32_t qb = sb + (((mt + 1) & 1) ? P2_Q1 : P2_Q0);
            uint32_t vb = sb + (((mt + 1) & 1) ? P2_V1 : P2_V0);
            P2_STAGE(qb, vb, (mt + 1) * 128);
            CP_COMMIT();
        }
        const __half* Qc = (const __half*)(smraw + ((mt & 1) ? P2_Q1 : P2_Q0));
        const __half* Vc = (const __half*)(smraw + ((mt & 1) ? P2_V1 : P2_V0));

#pragma unroll
        for (int t = 0; t < 8; t++) {
            float a0A[4] = {0.f,0.f,0.f,0.f}, a1A[4] = {0.f,0.f,0.f,0.f};
            float a0B[4] = {0.f,0.f,0.f,0.f}, a1B[4] = {0.f,0.f,0.f,0.f};
#pragma unroll
            for (int ks = 0; ks < 4; ks++) {
                int co = 16 * (ks ^ (g & 3)) + 4 * q;
                uint2 q0 = *(const uint2*)&Qc[(16 * t + g) * 64 + co];
                uint2 q1 = *(const uint2*)&Qc[(16 * t + 8 + g) * 64 + co];
                mma16(a0A, Ka0[ks][0], Ka0[ks][1], Ka0[ks][2], Ka0[ks][3], q0.x, q0.y);
                mma16(a1A, Ka0[ks][0], Ka0[ks][1], Ka0[ks][2], Ka0[ks][3], q1.x, q1.y);
                mma16(a0B, Ka1[ks][0], Ka1[ks][1], Ka1[ks][2], Ka1[ks][3], q0.x, q0.y);
                mma16(a1B, Ka1[ks][0], Ka1[ks][1], Ka1[ks][2], Ka1[ks][3], q1.x, q1.y);
            }
            uint32_t pxA0 = ex2h2(packh2(a0A[0], a0A[1]));
            uint32_t pxA1 = ex2h2(packh2(a0A[2], a0A[3]));
            uint32_t pyA0 = ex2h2(packh2(a1A[0], a1A[1]));
            uint32_t pyA1 = ex2h2(packh2(a1A[2], a1A[3]));
            uint32_t pxB0 = ex2h2(packh2(a0B[0], a0B[1]));
            uint32_t pxB1 = ex2h2(packh2(a0B[2], a0B[3]));
            uint32_t pyB0 = ex2h2(packh2(a1B[0], a1B[1]));
            uint32_t pyB1 = ex2h2(packh2(a1B[2], a1B[3]));

#pragma unroll
            for (int n = 0; n < 8; n++) {
                uint2 bb = *(const uint2*)&Vc[(8 * n + g) * 128 + 16 * (t ^ (g & 3)) + 4 * q];
                mma16(y0[n], pxA0, pxA1, pyA0, pyA1, bb.x, bb.y);
                mma16(y1[n], pxB0, pxB1, pyB0, pyB1, bb.x, bb.y);
            }
        }
    }

    float* ob0 = out + ((size_t)b * LL + l0 + r0) * CC;
    float* ob1 = out + ((size_t)b * LL + l0 + r0 + 16) * CC;
#pragma unroll
    for (int n = 0; n < 8; n++) {
        *(float2*)&ob0[(size_t)g * CC + 8 * n + 2 * q]       = make_float2(y0[n][0], y0[n][1]);
        *(float2*)&ob0[(size_t)(g + 8) * CC + 8 * n + 2 * q] = make_float2(y0[n][2], y0[n][3]);
        *(float2*)&ob1[(size_t)g * CC + 8 * n + 2 * q]       = make_float2(y1[n][0], y1[n][1]);
        *(float2*)&ob1[(size_t)(g + 8) * CC + 8 * n + 2 * q] = make_float2(y1[n][2], y1[n][3]);
    }
}

// ---------------------------------------------------------------------------
extern "C" void kernel_launch(void* const* d_in, const int* in_sizes, int n_in,
                              void* d_out, int out_size) {
    const float* x  = (const float*)d_in[0];
    const float* Wk = (const float*)d_in[1];
    const float* bk = (const float*)d_in[2];
    const float* Wq = (const float*)d_in[3];
    const float* bq = (const float*)d_in[4];
    const float* Wv = (const float*)d_in[5];
    const float* bv = (const float*)d_in[6];
    const void*  sl = (const void*)d_in[7];
    float* out = (float*)d_out;

    const int kq_smem = KQ_TOT * (int)sizeof(float);
    const int p1_smem = 2 * 128 * LDQH * 2 + 4 * 128 * (int)sizeof(float);
    const int p2_smem = P2_TOT;

    static bool attr_set = false;
    if (!attr_set) {
        cudaFuncSetAttribute(kqv_mma, cudaFuncAttributeMaxDynamicSharedMemorySize, kq_smem);
        cudaFuncSetAttribute(pass1,   cudaFuncAttributeMaxDynamicSharedMemorySize, p1_smem);
        cudaFuncSetAttribute(pass2,   cudaFuncAttributeMaxDynamicSharedMemorySize, p2_smem);
        attr_set = true;
    }

    dim3 g1(NLT, BB);
    kqv_mma<<<g1, 256, kq_smem>>>(x, Wk, bk, Wq, bq, Wv, bv, sl);

    dim3 g2(NLT, BB);
    pass1<<<g2, 128, p1_smem>>>();

    dim3 g3(LL / 64, BB);
    prep_kernel<<<g3, 256>>>();

    dim3 g4(NLT, BB);
    pass2<<<g4, 128, p2_smem>>>(out);
}

// round 16
// speedup vs baseline: 1.9716x; 1.0176x over previous
#include <cuda_runtime.h>
#include <cuda_fp16.h>
#include <math.h>
#include <stdint.h>

// Problem constants
#define BB 32
#define CC 64
#define LL 2048
#define DD 50
#define DK 64
#define TL 128
#define NLT (LL/TL)    // 16
#define NMT (LL/128)   // 16

// Scratch (device globals — allocation is forbidden)
// g_Kh/g_Qh: fp16, d interleaved within 16-chunks: pos 4q..4q+3 hold d = 2q,2q+1,2q+8,2q+9.
// g_Kh pre-scaled by log2e/sqrt(sample_len).
__device__ __half g_Kh[BB*LL*DK];
__device__ __half g_Qh[BB*LL*DK];
__device__ float  g_V[BB*LL*CC];          // tanh(xWv+bv), [m][c] fp32
__device__ __half g_Vph[BB*CC*LL];        // V' = V*cinv, [c][m'] perm16 on m
__device__ float  g_part[NLT*BB*LL];      // per-ltile column partials

__device__ __forceinline__ float read_len(const void* p) {
    int i = *(const int*)p;
    if (i > 0 && i < (1 << 24)) return (float)i;
    return __int_as_float(i);
}
__device__ __forceinline__ uint32_t smem_u32(const void* p) {
    uint32_t a;
    asm("{ .reg .u64 t; cvta.to.shared.u64 t, %1; cvt.u32.u64 %0, t; }" : "=r"(a) : "l"(p));
    return a;
}
__device__ __forceinline__ void cpa16(uint32_t dst, const void* src) {
    asm volatile("cp.async.cg.shared.global [%0], [%1], 16;" :: "r"(dst), "l"(src));
}
#define CP_COMMIT() asm volatile("cp.async.commit_group;" ::: "memory")
#define CP_WAIT0()  asm volatile("cp.async.wait_group 0;" ::: "memory")

__device__ __forceinline__ uint32_t f2tf32(float x) {
    uint32_t u;
    asm("cvt.rna.tf32.f32 %0, %1;" : "=r"(u) : "f"(x));
    return u;
}
__device__ __forceinline__ uint32_t packh2(float lo, float hi) {
    __half2 h = __floats2half2_rn(lo, hi);
    return *(uint32_t*)&h;
}
__device__ __forceinline__ uint32_t ex2h2(uint32_t v) {
    uint32_t r;
    asm("ex2.approx.f16x2 %0, %1;" : "=r"(r) : "r"(v));
    return r;
}
// D += A(16x8 tf32) * B(8x8 tf32)
__device__ __forceinline__ void mma8(float* d, const uint32_t* a, uint32_t b0, uint32_t b1) {
    asm volatile("mma.sync.aligned.m16n8k8.row.col.f32.tf32.tf32.f32 "
                 "{%0,%1,%2,%3}, {%4,%5,%6,%7}, {%8,%9}, {%0,%1,%2,%3};"
                 : "+f"(d[0]), "+f"(d[1]), "+f"(d[2]), "+f"(d[3])
                 : "r"(a[0]), "r"(a[1]), "r"(a[2]), "r"(a[3]), "r"(b0), "r"(b1));
}
// D += A(16x16 f16) * B(16x8 f16)
__device__ __forceinline__ void mma16(float* d, uint32_t a0, uint32_t a1, uint32_t a2,
                                      uint32_t a3, uint32_t b0, uint32_t b1) {
    asm volatile("mma.sync.aligned.m16n8k16.row.col.f32.f16.f16.f32 "
                 "{%0,%1,%2,%3}, {%4,%5,%6,%7}, {%8,%9}, {%0,%1,%2,%3};"
                 : "+f"(d[0]), "+f"(d[1]), "+f"(d[2]), "+f"(d[3])
                 : "r"(a0), "r"(a1), "r"(a2), "r"(a3), "r"(b0), "r"(b1));
}

// ---------------------------------------------------------------------------
// Kernel 1: projections via tf32 mma8. grid (16, 32), 256 thr (8 warps x 16 l).
// Staging aliases the x tile; weights stored fp16 (10-bit mantissa == tf32
// rounding for normal-range values). smem ~61KB -> 3 CTAs/SM.
// ---------------------------------------------------------------------------
#define LDX 136
#define LDWH 72        // Wsm leading dim in halves (36 half2 words/row)
#define LDS_T 68       // staging leading dim (floats); 128*68 == 64*136
#define KQ_XS   0
#define KQ_WS   (64*136)                    // float offset of Wsm
#define KQ_BIA  (KQ_WS + (176*LDWH)/2)      // float offset of bias
#define KQ_TOT  (KQ_BIA + 176)

__global__ __launch_bounds__(256, 3) void kqv_mma(
        const float* __restrict__ x,
        const float* __restrict__ Wk, const float* __restrict__ bk,
        const float* __restrict__ Wq, const float* __restrict__ bq,
        const float* __restrict__ Wv, const float* __restrict__ bv,
        const void* __restrict__ slp) {
    extern __shared__ float sm[];
    float*  xs   = sm + KQ_XS;          // [64][136]
    float*  stg  = sm + KQ_XS;          // [128][68] — aliases xs
    __half* Wsm  = (__half*)(sm + KQ_WS);  // [176][72] halves
    float*  bias = sm + KQ_BIA;

    const int tid = threadIdx.x;
    const int lane = tid & 31;
    const int wid = tid >> 5;
    const int g = lane >> 2, q = lane & 3;
    const int b = blockIdx.y;
    const int l0 = blockIdx.x * 128;
    const int r0 = wid * 16;
    const float kscale = rsqrtf(read_len(slp)) * 1.4426950408889634f;

    for (int idx = tid; idx < 56 * 64; idx += 256) {
        int d = idx >> 6, c = idx & 63;
        int pos = (c & ~7) | ((c & 3) << 1) | ((c >> 2) & 1);
        Wsm[d * LDWH + pos]        = (d < DD) ? __float2half(Wk[c * DD + d]) : __half(0.f);
        Wsm[(56 + d) * LDWH + pos] = (d < DD) ? __float2half(Wq[c * DD + d]) : __half(0.f);
    }
    for (int idx = tid; idx < 64 * 64; idx += 256) {
        int o = idx >> 6, c = idx & 63;
        int pos = (c & ~7) | ((c & 3) << 1) | ((c >> 2) & 1);
        Wsm[(112 + o) * LDWH + pos] = __float2half(Wv[c * CC + o]);
    }
    if (tid < 56)  bias[tid]       = (tid < DD) ? bk[tid] : 0.0f;
    if (tid < 56)  bias[56 + tid]  = (tid < DD) ? bq[tid] : 0.0f;
    if (tid < 64)  bias[112 + tid] = bv[tid];

    for (int idx = tid; idx < 64 * 32; idx += 256) {
        int row = idx >> 5, c4 = idx & 31;
        float4 v = *(const float4*)(x + (size_t)b * CC * LL + (size_t)row * LL + l0 + 4 * c4);
        v.x = __uint_as_float(f2tf32(v.x)); v.y = __uint_as_float(f2tf32(v.y));
        v.z = __uint_as_float(f2tf32(v.z)); v.w = __uint_as_float(f2tf32(v.w));
        *(float4*)&xs[row * LDX + 4 * c4] = v;
    }
    __syncthreads();

    uint32_t xa[8][4];
#pragma unroll
    for (int ks = 0; ks < 8; ks++) {
        xa[ks][0] = __float_as_uint(xs[(8 * ks + q) * LDX + r0 + g]);
        xa[ks][1] = __float_as_uint(xs[(8 * ks + q) * LDX + r0 + g + 8]);
        xa[ks][2] = __float_as_uint(xs[(8 * ks + q + 4) * LDX + r0 + g]);
        xa[ks][3] = __float_as_uint(xs[(8 * ks + q + 4) * LDX + r0 + g + 8]);
    }
    __syncthreads();   // xs now dead; stg may overwrite it

    const __half2* W2 = (const __half2*)Wsm;

    // ---- K ----
#pragma unroll
    for (int nt = 0; nt < 7; nt++) {
        float acc[4] = {0.f, 0.f, 0.f, 0.f};
#pragma unroll
        for (int ks = 0; ks < 8; ks++) {
            float2 bb = __half22float2(W2[(8 * nt + g) * (LDWH / 2) + 4 * ks + q]);
            mma8(acc, xa[ks], __float_as_uint(bb.x), __float_as_uint(bb.y));
        }
        float b0 = bias[8 * nt + 2 * q], b1 = bias[8 * nt + 2 * q + 1];
        float v0 = acc[0] + b0, v1 = acc[1] + b1, v2 = acc[2] + b0, v3 = acc[3] + b1;
        v0 = (v0 > 0.f) ? v0 : expm1f(v0); v1 = (v1 > 0.f) ? v1 : expm1f(v1);
        v2 = (v2 > 0.f) ? v2 : expm1f(v2); v3 = (v3 > 0.f) ? v3 : expm1f(v3);
        *(float2*)&stg[(r0 + g) * LDS_T + 8 * nt + 2 * q]     = make_float2(v0, v1);
        *(float2*)&stg[(r0 + g + 8) * LDS_T + 8 * nt + 2 * q] = make_float2(v2, v3);
    }
    for (int idx = tid; idx < 128 * 8; idx += 256)
        stg[(idx >> 3) * LDS_T + 56 + (idx & 7)] = 0.0f;
    __syncthreads();
    for (int idx = tid; idx < 128 * 32; idx += 256) {
        int row = idx >> 5, p = (idx & 31) * 2;
        int pl = p & 15;
        int d0 = (p & ~15) + 2 * ((pl >> 2) & 3) + 8 * ((pl >> 1) & 1);
        __half2 h = __floats2half2_rn(stg[row * LDS_T + d0] * kscale,
                                      stg[row * LDS_T + d0 + 1] * kscale);
        *(__half2*)(g_Kh + ((size_t)b * LL + l0 + row) * DK + p) = h;
    }
    __syncthreads();

    // ---- Q ----
#pragma unroll
    for (int nt = 0; nt < 7; nt++) {
        float acc[4] = {0.f, 0.f, 0.f, 0.f};
#pragma unroll
        for (int ks = 0; ks < 8; ks++) {
            float2 bb = __half22float2(W2[(56 + 8 * nt + g) * (LDWH / 2) + 4 * ks + q]);
            mma8(acc, xa[ks], __float_as_uint(bb.x), __float_as_uint(bb.y));
        }
        float b0 = bias[56 + 8 * nt + 2 * q], b1 = bias[56 + 8 * nt + 2 * q + 1];
        float v0 = acc[0] + b0, v1 = acc[1] + b1, v2 = acc[2] + b0, v3 = acc[3] + b1;
        v0 = (v0 > 0.f) ? v0 : expm1f(v0); v1 = (v1 > 0.f) ? v1 : expm1f(v1);
        v2 = (v2 > 0.f) ? v2 : expm1f(v2); v3 = (v3 > 0.f) ? v3 : expm1f(v3);
        *(float2*)&stg[(r0 + g) * LDS_T + 8 * nt + 2 * q]     = make_float2(v0, v1);
        *(float2*)&stg[(r0 + g + 8) * LDS_T + 8 * nt + 2 * q] = make_float2(v2, v3);
    }
    for (int idx = tid; idx < 128 * 8; idx += 256)
        stg[(idx >> 3) * LDS_T + 56 + (idx & 7)] = 0.0f;
    __syncthreads();
    for (int idx = tid; idx < 128 * 32; idx += 256) {
        int row = idx >> 5, p = (idx & 31) * 2;
        int pl = p & 15;
        int d0 = (p & ~15) + 2 * ((pl >> 2) & 3) + 8 * ((pl >> 1) & 1);
        __half2 h = __floats2half2_rn(stg[row * LDS_T + d0], stg[row * LDS_T + d0 + 1]);
        *(__half2*)(g_Qh + ((size_t)b * LL + l0 + row) * DK + p) = h;
    }
    __syncthreads();

    // ---- V ----
#pragma unroll
    for (int nt = 0; nt < 8; nt++) {
        float acc[4] = {0.f, 0.f, 0.f, 0.f};
#pragma unroll
        for (int ks = 0; ks < 8; ks++) {
            float2 bb = __half22float2(W2[(112 + 8 * nt + g) * (LDWH / 2) + 4 * ks + q]);
            mma8(acc, xa[ks], __float_as_uint(bb.x), __float_as_uint(bb.y));
        }
        float b0 = bias[112 + 8 * nt + 2 * q], b1 = bias[112 + 8 * nt + 2 * q + 1];
        *(float2*)&stg[(r0 + g) * LDS_T + 8 * nt + 2 * q] =
            make_float2(tanhf(acc[0] + b0), tanhf(acc[1] + b1));
        *(float2*)&stg[(r0 + g + 8) * LDS_T + 8 * nt + 2 * q] =
            make_float2(tanhf(acc[2] + b0), tanhf(acc[3] + b1));
    }
    __syncthreads();
    for (int idx = tid; idx < 128 * 16; idx += 256) {
        int row = idx >> 4, c4 = idx & 15;
        *(float4*)(g_V + ((size_t)b * LL + l0 + row) * CC + 4 * c4) =
            *(float4*)&stg[row * LDS_T + 4 * c4];
    }
}

// ---------------------------------------------------------------------------
// Kernel 2 (pass1): S fp16 GEMM -> ex2.f16x2 -> column partials.
// 4 warps x 32 rows (2x B-frag reuse), XOR-swizzled packed 16KB Q tiles,
// cp.async double-buffered. smem 34KB -> 5 CTAs/SM. grid (NLT, BB), 128 thr.
// Q layout: halves = row*64 + 16*(chunk ^ (row&3)) + in-chunk(0..15)
// ---------------------------------------------------------------------------
#define P1_Q0 0
#define P1_Q1 16384
#define P1_RED 32768
#define P1_TOT (32768 + 4*128*4)

__global__ __launch_bounds__(128, 5) void pass1(void) {
    extern __shared__ char smraw[];
    float* red = (float*)(smraw + P1_RED);           // [4][128]
    const uint32_t sb = smem_u32(smraw);

    const int tid = threadIdx.x;
    const int lane = tid & 31;
    const int wid = tid >> 5;          // 0..3
    const int g = lane >> 2, q = lane & 3;
    const int b = blockIdx.y;
    const int l0 = blockIdx.x * TL;
    const int r0 = wid * 32;

    uint32_t Ka0[4][4], Ka1[4][4];
#pragma unroll
    for (int ks = 0; ks < 4; ks++) {
        uint2 lo = *(const uint2*)(g_Kh + ((size_t)b * LL + l0 + r0 + g) * DK + 16 * ks + 4 * q);
        uint2 hi = *(const uint2*)(g_Kh + ((size_t)b * LL + l0 + r0 + g + 8) * DK + 16 * ks + 4 * q);
        Ka0[ks][0] = lo.x; Ka0[ks][2] = lo.y;
        Ka0[ks][1] = hi.x; Ka0[ks][3] = hi.y;
        uint2 lo1 = *(const uint2*)(g_Kh + ((size_t)b * LL + l0 + r0 + 16 + g) * DK + 16 * ks + 4 * q);
        uint2 hi1 = *(const uint2*)(g_Kh + ((size_t)b * LL + l0 + r0 + 24 + g) * DK + 16 * ks + 4 * q);
        Ka1[ks][0] = lo1.x; Ka1[ks][2] = lo1.y;
        Ka1[ks][1] = hi1.x; Ka1[ks][3] = hi1.y;
    }

#define P1_STAGE(qbase, m0_)                                                        \
    do {                                                                            \
        const __half* qsrc = g_Qh + ((size_t)b * LL + (m0_)) * DK;                  \
        for (int idx = tid; idx < 1024; idx += 128) {                               \
            int row = idx >> 3, c8 = idx & 7;                                       \
            uint32_t d = (qbase) + (uint32_t)(row * 128 +                           \
                          32 * (((c8 >> 1) ^ (row & 3))) + 16 * (c8 & 1));          \
            cpa16(d, qsrc + (size_t)row * DK + 8 * c8);                             \
        }                                                                           \
    } while (0)

    P1_STAGE(sb + P1_Q0, 0);
    CP_COMMIT();

    for (int mt = 0; mt < NMT; mt++) {
        CP_WAIT0();
        __syncthreads();
        if (mt < NMT - 1) {
            uint32_t qd = sb + (((mt + 1) & 1) ? P1_Q1 : P1_Q0);
            P1_STAGE(qd, (mt + 1) * 128);
            CP_COMMIT();
        }
        const __half* Qc = (const __half*)(smraw + ((mt & 1) ? P1_Q1 : P1_Q0));
        const int m0 = mt * 128;

#pragma unroll
        for (int t = 0; t < 8; t++) {
            float a0A[4] = {0.f,0.f,0.f,0.f}, a1A[4] = {0.f,0.f,0.f,0.f};
            float a0B[4] = {0.f,0.f,0.f,0.f}, a1B[4] = {0.f,0.f,0.f,0.f};
#pragma unroll
            for (int ks = 0; ks < 4; ks++) {
                int co = 16 * (ks ^ (g & 3)) + 4 * q;
                uint2 q0 = *(const uint2*)&Qc[(16 * t + g) * 64 + co];
                uint2 q1 = *(const uint2*)&Qc[(16 * t + 8 + g) * 64 + co];
                mma16(a0A, Ka0[ks][0], Ka0[ks][1], Ka0[ks][2], Ka0[ks][3], q0.x, q0.y);
                mma16(a1A, Ka0[ks][0], Ka0[ks][1], Ka0[ks][2], Ka0[ks][3], q1.x, q1.y);
                mma16(a0B, Ka1[ks][0], Ka1[ks][1], Ka1[ks][2], Ka1[ks][3], q0.x, q0.y);
                mma16(a1B, Ka1[ks][0], Ka1[ks][1], Ka1[ks][2], Ka1[ks][3], q1.x, q1.y);
            }
            uint32_t pxA0 = ex2h2(packh2(a0A[0], a0A[1]));
            uint32_t pxA1 = ex2h2(packh2(a0A[2], a0A[3]));
            uint32_t pyA0 = ex2h2(packh2(a1A[0], a1A[1]));
            uint32_t pyA1 = ex2h2(packh2(a1A[2], a1A[3]));
            uint32_t pxB0 = ex2h2(packh2(a0B[0], a0B[1]));
            uint32_t pxB1 = ex2h2(packh2(a0B[2], a0B[3]));
            uint32_t pyB0 = ex2h2(packh2(a1B[0], a1B[1]));
            uint32_t pyB1 = ex2h2(packh2(a1B[2], a1B[3]));

            // column partials over the warp's 32 rows
            __half2 h0 = __hadd2(__hadd2(*(__half2*)&pxA0, *(__half2*)&pxA1),
                                 __hadd2(*(__half2*)&pxB0, *(__half2*)&pxB1));
            __half2 h1 = __hadd2(__hadd2(*(__half2*)&pyA0, *(__half2*)&pyA1),
                                 __hadd2(*(__half2*)&pyB0, *(__half2*)&pyB1));
#pragma unroll
            for (int off = 4; off < 32; off <<= 1) {
                uint32_t u0 = __shfl_xor_sync(0xFFFFFFFFu, *(uint32_t*)&h0, off);
                uint32_t u1 = __shfl_xor_sync(0xFFFFFFFFu, *(uint32_t*)&h1, off);
                h0 = __hadd2(h0, *(__half2*)&u0);
                h1 = __hadd2(h1, *(__half2*)&u1);
            }
            if (lane < 4) {
                float2 f0 = __half22float2(h0);
                float2 f1 = __half22float2(h1);
                red[wid * 128 + 16 * t + 2 * q]         = f0.x;
                red[wid * 128 + 16 * t + 2 * q + 1]     = f0.y;
                red[wid * 128 + 16 * t + 8 + 2 * q]     = f1.x;
                red[wid * 128 + 16 * t + 8 + 2 * q + 1] = f1.y;
            }
        }
        __syncthreads();
        {
            float s = red[tid] + red[128 + tid] + red[256 + tid] + red[384 + tid];
            g_part[((size_t)blockIdx.x * BB + b) * LL + m0 + tid] = s;
        }
    }
}

// ---------------------------------------------------------------------------
// Kernel 3: cinv; V' = fp16(V*cinv) transposed [c][m'] perm16.
// ---------------------------------------------------------------------------
__global__ void prep_kernel() {
    __shared__ float ci[64];
    __shared__ float vt[64 * 68];
    const int tid = threadIdx.x;
    const int b = blockIdx.y;
    const int m0 = blockIdx.x * 64;

    if (tid < 64) {
        float s = 0.0f;
#pragma unroll
        for (int lt = 0; lt < NLT; lt++)
            s += g_part[((size_t)lt * BB + b) * LL + m0 + tid];
        ci[tid] = 1.0f / s;
    }
    for (int idx = tid; idx < 64 * 16; idx += 256) {
        int row = idx >> 4, c4 = idx & 15;
        *(float4*)&vt[row * 68 + 4 * c4] =
            *(const float4*)(g_V + ((size_t)b * LL + m0 + row) * CC + 4 * c4);
    }
    __syncthreads();
    for (int idx = tid; idx < 64 * 32; idx += 256) {
        int c = idx >> 5, jp = idx & 31;
        int m = 16 * (jp >> 3) + 8 * (jp & 1) + 2 * ((jp >> 1) & 3);
        __half2 hv = __floats2half2_rn(vt[m * 68 + c] * ci[m],
                                       vt[(m + 1) * 68 + c] * ci[m + 1]);
        *(__half2*)(g_Vph + ((size_t)b * CC + c) * LL + m0 + 2 * jp) = hv;
    }
}

// ---------------------------------------------------------------------------
// Kernel 4 (pass2): fused S GEMM -> exp -> Y GEMM (R14/R15 version, unchanged):
// 4 warps x 32 rows, 2x B-frag reuse, XOR-swizzled packed tiles, cp.async
// double-buffered. grid (NLT, BB), 128 thr.
// ---------------------------------------------------------------------------
#define P2_Q0 0
#define P2_Q1 16384
#define P2_V0 32768
#define P2_V1 49152
#define P2_TOT 65536

__global__ __launch_bounds__(128, 3) void pass2(float* __restrict__ out) {
    extern __shared__ char smraw[];
    const uint32_t sb = smem_u32(smraw);

    const int tid = threadIdx.x;
    const int lane = tid & 31;
    const int wid = tid >> 5;
    const int g = lane >> 2, q = lane & 3;
    const int b = blockIdx.y;
    const int l0 = blockIdx.x * TL;
    const int r0 = wid * 32;

    uint32_t Ka0[4][4], Ka1[4][4];
#pragma unroll
    for (int ks = 0; ks < 4; ks++) {
        uint2 lo = *(const uint2*)(g_Kh + ((size_t)b * LL + l0 + r0 + g) * DK + 16 * ks + 4 * q);
        uint2 hi = *(const uint2*)(g_Kh + ((size_t)b * LL + l0 + r0 + g + 8) * DK + 16 * ks + 4 * q);
        Ka0[ks][0] = lo.x; Ka0[ks][2] = lo.y;
        Ka0[ks][1] = hi.x; Ka0[ks][3] = hi.y;
        uint2 lo1 = *(const uint2*)(g_Kh + ((size_t)b * LL + l0 + r0 + 16 + g) * DK + 16 * ks + 4 * q);
        uint2 hi1 = *(const uint2*)(g_Kh + ((size_t)b * LL + l0 + r0 + 24 + g) * DK + 16 * ks + 4 * q);
        Ka1[ks][0] = lo1.x; Ka1[ks][2] = lo1.y;
        Ka1[ks][1] = hi1.x; Ka1[ks][3] = hi1.y;
    }

    float y0[8][4], y1[8][4];
#pragma unroll
    for (int n = 0; n < 8; n++)
#pragma unroll
        for (int e = 0; e < 4; e++) { y0[n][e] = 0.f; y1[n][e] = 0.f; }

#define P2_STAGE(qbase, vbase, m0_)                                                 \
    do {                                                                            \
        const __half* qsrc = g_Qh + ((size_t)b * LL + (m0_)) * DK;                  \
        for (int idx = tid; idx < 1024; idx += 128) {                               \
            int row = idx >> 3, c8 = idx & 7;                                       \
            uint32_t d = (qbase) + (uint32_t)(row * 128 +                           \
                          32 * (((c8 >> 1) ^ (row & 3))) + 16 * (c8 & 1));          \
            cpa16(d, qsrc + (size_t)row * DK + 8 * c8);                             \
        }                                                                           \
        const __half* vsrc = g_Vph + (size_t)b * CC * LL + (m0_);                   \
        for (int idx = tid; idx < 1024; idx += 128) {                               \
            int row = idx >> 4, c8 = idx & 15;                                      \
            uint32_t d = (vbase) + (uint32_t)(row * 256 +                           \
                          32 * (((c8 >> 1) ^ (row & 3))) + 16 * (c8 & 1));          \
            cpa16(d, vsrc + (size_t)row * LL + 8 * c8);                             \
        }                                                                           \
    } while (0)

    P2_STAGE(sb + P2_Q0, sb + P2_V0, 0);
    CP_COMMIT();

    for (int mt = 0; mt < NMT; mt++) {
        CP_WAIT0();
        __syncthreads();
        if (mt < NMT - 1) {
            uint32_t qb = sb + (((mt + 1) & 1) ? P2_Q1 : P2_Q0);
            uint32_t vb = sb + (((mt + 1) & 1) ? P2_V1 : P2_V0);
            P2_STAGE(qb, vb, (mt + 1) * 128);
            CP_COMMIT();
        }
        const __half* Qc = (const __half*)(smraw + ((mt & 1) ? P2_Q1 : P2_Q0));
        const __half* Vc = (const __half*)(smraw + ((mt & 1) ? P2_V1 : P2_V0));

#pragma unroll
        for (int t = 0; t < 8; t++) {
            float a0A[4] = {0.f,0.f,0.f,0.f}, a1A[4] = {0.f,0.f,0.f,0.f};
            float a0B[4] = {0.f,0.f,0.f,0.f}, a1B[4] = {0.f,0.f,0.f,0.f};
#pragma unroll
            for (int ks = 0; ks < 4; ks++) {
                int co = 16 * (ks ^ (g & 3)) + 4 * q;
                uint2 q0 = *(const uint2*)&Qc[(16 * t + g) * 64 + co];
                uint2 q1 = *(const uint2*)&Qc[(16 * t + 8 + g) * 64 + co];
                mma16(a0A, Ka0[ks][0], Ka0[ks][1], Ka0[ks][2], Ka0[ks][3], q0.x, q0.y);
                mma16(a1A, Ka0[ks][0], Ka0[ks][1], Ka0[ks][2], Ka0[ks][3], q1.x, q1.y);
                mma16(a0B, Ka1[ks][0], Ka1[ks][1], Ka1[ks][2], Ka1[ks][3], q0.x, q0.y);
                mma16(a1B, Ka1[ks][0], Ka1[ks][1], Ka1[ks][2], Ka1[ks][3], q1.x, q1.y);
            }
            uint32_t pxA0 = ex2h2(packh2(a0A[0], a0A[1]));
            uint32_t pxA1 = ex2h2(packh2(a0A[2], a0A[3]));
            uint32_t pyA0 = ex2h2(packh2(a1A[0], a1A[1]));
            uint32_t pyA1 = ex2h2(packh2(a1A[2], a1A[3]));
            uint32_t pxB0 = ex2h2(packh2(a0B[0], a0B[1]));
            uint32_t pxB1 = ex2h2(packh2(a0B[2], a0B[3]));
            uint32_t pyB0 = ex2h2(packh2(a1B[0], a1B[1]));
            uint32_t pyB1 = ex2h2(packh2(a1B[2], a1B[3]));

#pragma unroll
            for (int n = 0; n < 8; n++) {
                uint2 bb = *(const uint2*)&Vc[(8 * n + g) * 128 + 16 * (t ^ (g & 3)) + 4 * q];
                mma16(y0[n], pxA0, pxA1, pyA0, pyA1, bb.x, bb.y);
                mma16(y1[n], pxB0, pxB1, pyB0, pyB1, bb.x, bb.y);
            }
        }
    }

    float* ob0 = out + ((size_t)b * LL + l0 + r0) * CC;
    float* ob1 = out + ((size_t)b * LL + l0 + r0 + 16) * CC;
#pragma unroll
    for (int n = 0; n < 8; n++) {
        *(float2*)&ob0[(size_t)g * CC + 8 * n + 2 * q]       = make_float2(y0[n][0], y0[n][1]);
        *(float2*)&ob0[(size_t)(g + 8) * CC + 8 * n + 2 * q] = make_float2(y0[n][2], y0[n][3]);
        *(float2*)&ob1[(size_t)g * CC + 8 * n + 2 * q]       = make_float2(y1[n][0], y1[n][1]);
        *(float2*)&ob1[(size_t)(g + 8) * CC + 8 * n + 2 * q] = make_float2(y1[n][2], y1[n][3]);
    }
}

// ---------------------------------------------------------------------------
extern "C" void kernel_launch(void* const* d_in, const int* in_sizes, int n_in,
                              void* d_out, int out_size) {
    const float* x  = (const float*)d_in[0];
    const float* Wk = (const float*)d_in[1];
    const float* bk = (const float*)d_in[2];
    const float* Wq = (const float*)d_in[3];
    const float* bq = (const float*)d_in[4];
    const float* Wv = (const float*)d_in[5];
    const float* bv = (const float*)d_in[6];
    const void*  sl = (const void*)d_in[7];
    float* out = (float*)d_out;

    const int kq_smem = KQ_TOT * (int)sizeof(float);
    const int p1_smem = P1_TOT;
    const int p2_smem = P2_TOT;

    static bool attr_set = false;
    if (!attr_set) {
        cudaFuncSetAttribute(kqv_mma, cudaFuncAttributeMaxDynamicSharedMemorySize, kq_smem);
        cudaFuncSetAttribute(pass1,   cudaFuncAttributeMaxDynamicSharedMemorySize, p1_smem);
        cudaFuncSetAttribute(pass2,   cudaFuncAttributeMaxDynamicSharedMemorySize, p2_smem);
        attr_set = true;
    }

    dim3 g1(NLT, BB);
    kqv_mma<<<g1, 256, kq_smem>>>(x, Wk, bk, Wq, bq, Wv, bv, sl);

    dim3 g2(NLT, BB);
    pass1<<<g2, 128, p1_smem>>>();

    dim3 g3(LL / 64, BB);
    prep_kernel<<<g3, 256>>>();

    dim3 g4(NLT, BB);
    pass2<<<g4, 128, p2_smem>>>(out);
}

// round 17
// speedup vs baseline: 2.0785x; 1.0542x over previous
#include <cuda_runtime.h>
#include <cuda_fp16.h>
#include <math.h>
#include <stdint.h>

// Problem constants
#define BB 32
#define CC 64
#define LL 2048
#define DD 50
#define DK 64
#define TL 128
#define NLT (LL/TL)    // 16
#define NMT (LL/128)   // 16

// Scratch (device globals — allocation is forbidden)
// g_Kh/g_Qh: fp16, d interleaved within 16-chunks: pos 4q..4q+3 hold d = 2q,2q+1,2q+8,2q+9.
// g_Kh pre-scaled by log2e/sqrt(sample_len).
__device__ __half g_Kh[BB*LL*DK];
__device__ __half g_Qh[BB*LL*DK];
__device__ float  g_V[BB*LL*CC];          // tanh(xWv+bv), [m][c] fp32
__device__ __half g_Vph[BB*CC*LL];        // V' = V*cinv, [c][m'] perm16 on m
__device__ float  g_part[NLT*BB*LL];      // per-ltile column partials
__device__ __half g_Wh[176*72];           // preprocessed weights (swizzled fp16)
__device__ float  g_biasp[176];           // padded bias [K 0..55 | Q 56..111 | V 112..175]

__device__ __forceinline__ float read_len(const void* p) {
    int i = *(const int*)p;
    if (i > 0 && i < (1 << 24)) return (float)i;
    return __int_as_float(i);
}
__device__ __forceinline__ uint32_t smem_u32(const void* p) {
    uint32_t a;
    asm("{ .reg .u64 t; cvta.to.shared.u64 t, %1; cvt.u32.u64 %0, t; }" : "=r"(a) : "l"(p));
    return a;
}
__device__ __forceinline__ void cpa16(uint32_t dst, const void* src) {
    asm volatile("cp.async.cg.shared.global [%0], [%1], 16;" :: "r"(dst), "l"(src));
}
#define CP_COMMIT() asm volatile("cp.async.commit_group;" ::: "memory")
#define CP_WAIT0()  asm volatile("cp.async.wait_group 0;" ::: "memory")

__device__ __forceinline__ uint32_t f2tf32(float x) {
    uint32_t u;
    asm("cvt.rna.tf32.f32 %0, %1;" : "=r"(u) : "f"(x));
    return u;
}
__device__ __forceinline__ uint32_t packh2(float lo, float hi) {
    __half2 h = __floats2half2_rn(lo, hi);
    return *(uint32_t*)&h;
}
__device__ __forceinline__ uint32_t ex2h2(uint32_t v) {
    uint32_t r;
    asm("ex2.approx.f16x2 %0, %1;" : "=r"(r) : "r"(v));
    return r;
}
// D += A(16x8 tf32) * B(8x8 tf32)
__device__ __forceinline__ void mma8(float* d, const uint32_t* a, uint32_t b0, uint32_t b1) {
    asm volatile("mma.sync.aligned.m16n8k8.row.col.f32.tf32.tf32.f32 "
                 "{%0,%1,%2,%3}, {%4,%5,%6,%7}, {%8,%9}, {%0,%1,%2,%3};"
                 : "+f"(d[0]), "+f"(d[1]), "+f"(d[2]), "+f"(d[3])
                 : "r"(a[0]), "r"(a[1]), "r"(a[2]), "r"(a[3]), "r"(b0), "r"(b1));
}
// D += A(16x16 f16) * B(16x8 f16)
__device__ __forceinline__ void mma16(float* d, uint32_t a0, uint32_t a1, uint32_t a2,
                                      uint32_t a3, uint32_t b0, uint32_t b1) {
    asm volatile("mma.sync.aligned.m16n8k16.row.col.f32.f16.f16.f32 "
                 "{%0,%1,%2,%3}, {%4,%5,%6,%7}, {%8,%9}, {%0,%1,%2,%3};"
                 : "+f"(d[0]), "+f"(d[1]), "+f"(d[2]), "+f"(d[3])
                 : "r"(a0), "r"(a1), "r"(a2), "r"(a3), "r"(b0), "r"(b1));
}

#define LDWH 72        // weight image leading dim in halves

// ---------------------------------------------------------------------------
// Kernel 0 (setup): build swizzled fp16 weight image + padded bias, once.
// grid (32), 256 thr.
// ---------------------------------------------------------------------------
__global__ void setup_kernel(const float* __restrict__ Wk, const float* __restrict__ bk,
                             const float* __restrict__ Wq, const float* __restrict__ bq,
                             const float* __restrict__ Wv, const float* __restrict__ bv) {
    const int stride = gridDim.x * blockDim.x;
    const int t0 = blockIdx.x * blockDim.x + threadIdx.x;

    for (int idx = t0; idx < 56 * 64; idx += stride) {
        int d = idx >> 6, c = idx & 63;
        int pos = (c & ~7) | ((c & 3) << 1) | ((c >> 2) & 1);
        g_Wh[d * LDWH + pos]        = (d < DD) ? __float2half(Wk[c * DD + d]) : __half(0.f);
        g_Wh[(56 + d) * LDWH + pos] = (d < DD) ? __float2half(Wq[c * DD + d]) : __half(0.f);
    }
    for (int idx = t0; idx < 64 * 64; idx += stride) {
        int o = idx >> 6, c = idx & 63;
        int pos = (c & ~7) | ((c & 3) << 1) | ((c >> 2) & 1);
        g_Wh[(112 + o) * LDWH + pos] = __float2half(Wv[c * CC + o]);
    }
    // zero pad columns 64..71 of every row
    for (int idx = t0; idx < 176 * 8; idx += stride)
        g_Wh[(idx >> 3) * LDWH + 64 + (idx & 7)] = __half(0.f);
    for (int idx = t0; idx < 176; idx += stride) {
        float v;
        if (idx < 56)       v = (idx < DD) ? bk[idx] : 0.0f;
        else if (idx < 112) v = (idx - 56 < DD) ? bq[idx - 56] : 0.0f;
        else                v = bv[idx - 112];
        g_biasp[idx] = v;
    }
}

// ---------------------------------------------------------------------------
// Kernel 1: projections via tf32 mma8. grid (16, 32), 256 thr (8 warps x 16 l).
// Weights/bias staged via cp.async from the preprocessed image (coalesced,
// no per-CTA transpose/convert). Staging buffer aliases the x tile.
// ---------------------------------------------------------------------------
#define LDX 136
#define LDS_T 68       // staging leading dim (floats); 128*68 == 64*136
#define KQ_XS   0
#define KQ_WS   (64*136)                    // float offset of Wsm
#define KQ_BIA  (KQ_WS + (176*LDWH)/2)      // float offset of bias
#define KQ_TOT  (KQ_BIA + 176)

__global__ __launch_bounds__(256, 3) void kqv_mma(
        const float* __restrict__ x, const void* __restrict__ slp) {
    extern __shared__ float sm[];
    float*  xs   = sm + KQ_XS;             // [64][136]
    float*  stg  = sm + KQ_XS;             // [128][68] — aliases xs
    __half* Wsm  = (__half*)(sm + KQ_WS);  // [176][72] halves
    float*  bias = sm + KQ_BIA;

    const int tid = threadIdx.x;
    const int lane = tid & 31;
    const int wid = tid >> 5;
    const int g = lane >> 2, q = lane & 3;
    const int b = blockIdx.y;
    const int l0 = blockIdx.x * 128;
    const int r0 = wid * 16;
    const float kscale = rsqrtf(read_len(slp)) * 1.4426950408889634f;
    const uint32_t sb = smem_u32(sm);

    // weights: 1584 chunks; bias: 44 chunks (cp.async, coalesced)
    for (int idx = tid; idx < 1584; idx += 256)
        cpa16(sb + KQ_WS * 4 + idx * 16, (const char*)g_Wh + idx * 16);
    for (int idx = tid; idx < 44; idx += 256)
        cpa16(sb + KQ_BIA * 4 + idx * 16, (const char*)g_biasp + idx * 16);
    CP_COMMIT();

    for (int idx = tid; idx < 64 * 32; idx += 256) {
        int row = idx >> 5, c4 = idx & 31;
        float4 v = *(const float4*)(x + (size_t)b * CC * LL + (size_t)row * LL + l0 + 4 * c4);
        v.x = __uint_as_float(f2tf32(v.x)); v.y = __uint_as_float(f2tf32(v.y));
        v.z = __uint_as_float(f2tf32(v.z)); v.w = __uint_as_float(f2tf32(v.w));
        *(float4*)&xs[row * LDX + 4 * c4] = v;
    }
    CP_WAIT0();
    __syncthreads();

    uint32_t xa[8][4];
#pragma unroll
    for (int ks = 0; ks < 8; ks++) {
        xa[ks][0] = __float_as_uint(xs[(8 * ks + q) * LDX + r0 + g]);
        xa[ks][1] = __float_as_uint(xs[(8 * ks + q) * LDX + r0 + g + 8]);
        xa[ks][2] = __float_as_uint(xs[(8 * ks + q + 4) * LDX + r0 + g]);
        xa[ks][3] = __float_as_uint(xs[(8 * ks + q + 4) * LDX + r0 + g + 8]);
    }
    __syncthreads();   // xs now dead; stg may overwrite it

    const __half2* W2 = (const __half2*)Wsm;

    // ---- K ----
#pragma unroll
    for (int nt = 0; nt < 7; nt++) {
        float acc[4] = {0.f, 0.f, 0.f, 0.f};
#pragma unroll
        for (int ks = 0; ks < 8; ks++) {
            float2 bb = __half22float2(W2[(8 * nt + g) * (LDWH / 2) + 4 * ks + q]);
            mma8(acc, xa[ks], __float_as_uint(bb.x), __float_as_uint(bb.y));
        }
        float b0 = bias[8 * nt + 2 * q], b1 = bias[8 * nt + 2 * q + 1];
        float v0 = acc[0] + b0, v1 = acc[1] + b1, v2 = acc[2] + b0, v3 = acc[3] + b1;
        v0 = (v0 > 0.f) ? v0 : expm1f(v0); v1 = (v1 > 0.f) ? v1 : expm1f(v1);
        v2 = (v2 > 0.f) ? v2 : expm1f(v2); v3 = (v3 > 0.f) ? v3 : expm1f(v3);
        *(float2*)&stg[(r0 + g) * LDS_T + 8 * nt + 2 * q]     = make_float2(v0, v1);
        *(float2*)&stg[(r0 + g + 8) * LDS_T + 8 * nt + 2 * q] = make_float2(v2, v3);
    }
    for (int idx = tid; idx < 128 * 8; idx += 256)
        stg[(idx >> 3) * LDS_T + 56 + (idx & 7)] = 0.0f;
    __syncthreads();
    for (int idx = tid; idx < 128 * 32; idx += 256) {
        int row = idx >> 5, p = (idx & 31) * 2;
        int pl = p & 15;
        int d0 = (p & ~15) + 2 * ((pl >> 2) & 3) + 8 * ((pl >> 1) & 1);
        __half2 h = __floats2half2_rn(stg[row * LDS_T + d0] * kscale,
                                      stg[row * LDS_T + d0 + 1] * kscale);
        *(__half2*)(g_Kh + ((size_t)b * LL + l0 + row) * DK + p) = h;
    }
    __syncthreads();

    // ---- Q ----
#pragma unroll
    for (int nt = 0; nt < 7; nt++) {
        float acc[4] = {0.f, 0.f, 0.f, 0.f};
#pragma unroll
        for (int ks = 0; ks < 8; ks++) {
            float2 bb = __half22float2(W2[(56 + 8 * nt + g) * (LDWH / 2) + 4 * ks + q]);
            mma8(acc, xa[ks], __float_as_uint(bb.x), __float_as_uint(bb.y));
        }
        float b0 = bias[56 + 8 * nt + 2 * q], b1 = bias[56 + 8 * nt + 2 * q + 1];
        float v0 = acc[0] + b0, v1 = acc[1] + b1, v2 = acc[2] + b0, v3 = acc[3] + b1;
        v0 = (v0 > 0.f) ? v0 : expm1f(v0); v1 = (v1 > 0.f) ? v1 : expm1f(v1);
        v2 = (v2 > 0.f) ? v2 : expm1f(v2); v3 = (v3 > 0.f) ? v3 : expm1f(v3);
        *(float2*)&stg[(r0 + g) * LDS_T + 8 * nt + 2 * q]     = make_float2(v0, v1);
        *(float2*)&stg[(r0 + g + 8) * LDS_T + 8 * nt + 2 * q] = make_float2(v2, v3);
    }
    for (int idx = tid; idx < 128 * 8; idx += 256)
        stg[(idx >> 3) * LDS_T + 56 + (idx & 7)] = 0.0f;
    __syncthreads();
    for (int idx = tid; idx < 128 * 32; idx += 256) {
        int row = idx >> 5, p = (idx & 31) * 2;
        int pl = p & 15;
        int d0 = (p & ~15) + 2 * ((pl >> 2) & 3) + 8 * ((pl >> 1) & 1);
        __half2 h = __floats2half2_rn(stg[row * LDS_T + d0], stg[row * LDS_T + d0 + 1]);
        *(__half2*)(g_Qh + ((size_t)b * LL + l0 + row) * DK + p) = h;
    }
    __syncthreads();

    // ---- V ----
#pragma unroll
    for (int nt = 0; nt < 8; nt++) {
        float acc[4] = {0.f, 0.f, 0.f, 0.f};
#pragma unroll
        for (int ks = 0; ks < 8; ks++) {
            float2 bb = __half22float2(W2[(112 + 8 * nt + g) * (LDWH / 2) + 4 * ks + q]);
            mma8(acc, xa[ks], __float_as_uint(bb.x), __float_as_uint(bb.y));
        }
        float b0 = bias[112 + 8 * nt + 2 * q], b1 = bias[112 + 8 * nt + 2 * q + 1];
        *(float2*)&stg[(r0 + g) * LDS_T + 8 * nt + 2 * q] =
            make_float2(tanhf(acc[0] + b0), tanhf(acc[1] + b1));
        *(float2*)&stg[(r0 + g + 8) * LDS_T + 8 * nt + 2 * q] =
            make_float2(tanhf(acc[2] + b0), tanhf(acc[3] + b1));
    }
    __syncthreads();
    for (int idx = tid; idx < 128 * 16; idx += 256) {
        int row = idx >> 4, c4 = idx & 15;
        *(float4*)(g_V + ((size_t)b * LL + l0 + row) * CC + 4 * c4) =
            *(float4*)&stg[row * LDS_T + 4 * c4];
    }
}

// ---------------------------------------------------------------------------
// Kernel 2 (pass1): S fp16 GEMM -> ex2.f16x2 -> column partials.
// 4 warps x 32 rows (2x B-frag reuse), XOR-swizzled packed 16KB Q tiles,
// cp.async double-buffered. smem 34KB -> 5 CTAs/SM. grid (NLT, BB), 128 thr.
// ---------------------------------------------------------------------------
#define P1_Q0 0
#define P1_Q1 16384
#define P1_RED 32768
#define P1_TOT (32768 + 4*128*4)

__global__ __launch_bounds__(128, 5) void pass1(void) {
    extern __shared__ char smraw[];
    float* red = (float*)(smraw + P1_RED);           // [4][128]
    const uint32_t sb = smem_u32(smraw);

    const int tid = threadIdx.x;
    const int lane = tid & 31;
    const int wid = tid >> 5;          // 0..3
    const int g = lane >> 2, q = lane & 3;
    const int b = blockIdx.y;
    const int l0 = blockIdx.x * TL;
    const int r0 = wid * 32;

    uint32_t Ka0[4][4], Ka1[4][4];
#pragma unroll
    for (int ks = 0; ks < 4; ks++) {
        uint2 lo = *(const uint2*)(g_Kh + ((size_t)b * LL + l0 + r0 + g) * DK + 16 * ks + 4 * q);
        uint2 hi = *(const uint2*)(g_Kh + ((size_t)b * LL + l0 + r0 + g + 8) * DK + 16 * ks + 4 * q);
        Ka0[ks][0] = lo.x; Ka0[ks][2] = lo.y;
        Ka0[ks][1] = hi.x; Ka0[ks][3] = hi.y;
        uint2 lo1 = *(const uint2*)(g_Kh + ((size_t)b * LL + l0 + r0 + 16 + g) * DK + 16 * ks + 4 * q);
        uint2 hi1 = *(const uint2*)(g_Kh + ((size_t)b * LL + l0 + r0 + 24 + g) * DK + 16 * ks + 4 * q);
        Ka1[ks][0] = lo1.x; Ka1[ks][2] = lo1.y;
        Ka1[ks][1] = hi1.x; Ka1[ks][3] = hi1.y;
    }

#define P1_STAGE(qbase, m0_)                                                        \
    do {                                                                            \
        const __half* qsrc = g_Qh + ((size_t)b * LL + (m0_)) * DK;                  \
        for (int idx = tid; idx < 1024; idx += 128) {                               \
            int row = idx >> 3, c8 = idx & 7;                                       \
            uint32_t d = (qbase) + (uint32_t)(row * 128 +                           \
                          32 * (((c8 >> 1) ^ (row & 3))) + 16 * (c8 & 1));          \
            cpa16(d, qsrc + (size_t)row * DK + 8 * c8);                             \
        }                                                                           \
    } while (0)

    P1_STAGE(sb + P1_Q0, 0);
    CP_COMMIT();

    for (int mt = 0; mt < NMT; mt++) {
        CP_WAIT0();
        __syncthreads();
        if (mt < NMT - 1) {
            uint32_t qd = sb + (((mt + 1) & 1) ? P1_Q1 : P1_Q0);
            P1_STAGE(qd, (mt + 1) * 128);
            CP_COMMIT();
        }
        const __half* Qc = (const __half*)(smraw + ((mt & 1) ? P1_Q1 : P1_Q0));
        const int m0 = mt * 128;

#pragma unroll
        for (int t = 0; t < 8; t++) {
            float a0A[4] = {0.f,0.f,0.f,0.f}, a1A[4] = {0.f,0.f,0.f,0.f};
            float a0B[4] = {0.f,0.f,0.f,0.f}, a1B[4] = {0.f,0.f,0.f,0.f};
#pragma unroll
            for (int ks = 0; ks < 4; ks++) {
                int co = 16 * (ks ^ (g & 3)) + 4 * q;
                uint2 q0 = *(const uint2*)&Qc[(16 * t + g) * 64 + co];
                uint2 q1 = *(const uint2*)&Qc[(16 * t + 8 + g) * 64 + co];
                mma16(a0A, Ka0[ks][0], Ka0[ks][1], Ka0[ks][2], Ka0[ks][3], q0.x, q0.y);
                mma16(a1A, Ka0[ks][0], Ka0[ks][1], Ka0[ks][2], Ka0[ks][3], q1.x, q1.y);
                mma16(a0B, Ka1[ks][0], Ka1[ks][1], Ka1[ks][2], Ka1[ks][3], q0.x, q0.y);
                mma16(a1B, Ka1[ks][0], Ka1[ks][1], Ka1[ks][2], Ka1[ks][3], q1.x, q1.y);
            }
            uint32_t pxA0 = ex2h2(packh2(a0A[0], a0A[1]));
            uint32_t pxA1 = ex2h2(packh2(a0A[2], a0A[3]));
            uint32_t pyA0 = ex2h2(packh2(a1A[0], a1A[1]));
            uint32_t pyA1 = ex2h2(packh2(a1A[2], a1A[3]));
            uint32_t pxB0 = ex2h2(packh2(a0B[0], a0B[1]));
            uint32_t pxB1 = ex2h2(packh2(a0B[2], a0B[3]));
            uint32_t pyB0 = ex2h2(packh2(a1B[0], a1B[1]));
            uint32_t pyB1 = ex2h2(packh2(a1B[2], a1B[3]));

            __half2 h0 = __hadd2(__hadd2(*(__half2*)&pxA0, *(__half2*)&pxA1),
                                 __hadd2(*(__half2*)&pxB0, *(__half2*)&pxB1));
            __half2 h1 = __hadd2(__hadd2(*(__half2*)&pyA0, *(__half2*)&pyA1),
                                 __hadd2(*(__half2*)&pyB0, *(__half2*)&pyB1));
#pragma unroll
            for (int off = 4; off < 32; off <<= 1) {
                uint32_t u0 = __shfl_xor_sync(0xFFFFFFFFu, *(uint32_t*)&h0, off);
                uint32_t u1 = __shfl_xor_sync(0xFFFFFFFFu, *(uint32_t*)&h1, off);
                h0 = __hadd2(h0, *(__half2*)&u0);
                h1 = __hadd2(h1, *(__half2*)&u1);
            }
            if (lane < 4) {
                float2 f0 = __half22float2(h0);
                float2 f1 = __half22float2(h1);
                red[wid * 128 + 16 * t + 2 * q]         = f0.x;
                red[wid * 128 + 16 * t + 2 * q + 1]     = f0.y;
                red[wid * 128 + 16 * t + 8 + 2 * q]     = f1.x;
                red[wid * 128 + 16 * t + 8 + 2 * q + 1] = f1.y;
            }
        }
        __syncthreads();
        {
            float s = red[tid] + red[128 + tid] + red[256 + tid] + red[384 + tid];
            g_part[((size_t)blockIdx.x * BB + b) * LL + m0 + tid] = s;
        }
    }
}

// ---------------------------------------------------------------------------
// Kernel 3: cinv; V' = fp16(V*cinv) transposed [c][m'] perm16.
// ---------------------------------------------------------------------------
__global__ void prep_kernel() {
    __shared__ float ci[64];
    __shared__ float vt[64 * 68];
    const int tid = threadIdx.x;
    const int b = blockIdx.y;
    const int m0 = blockIdx.x * 64;

    if (tid < 64) {
        float s = 0.0f;
#pragma unroll
        for (int lt = 0; lt < NLT; lt++)
            s += g_part[((size_t)lt * BB + b) * LL + m0 + tid];
        ci[tid] = 1.0f / s;
    }
    for (int idx = tid; idx < 64 * 16; idx += 256) {
        int row = idx >> 4, c4 = idx & 15;
        *(float4*)&vt[row * 68 + 4 * c4] =
            *(const float4*)(g_V + ((size_t)b * LL + m0 + row) * CC + 4 * c4);
    }
    __syncthreads();
    for (int idx = tid; idx < 64 * 32; idx += 256) {
        int c = idx >> 5, jp = idx & 31;
        int m = 16 * (jp >> 3) + 8 * (jp & 1) + 2 * ((jp >> 1) & 3);
        __half2 hv = __floats2half2_rn(vt[m * 68 + c] * ci[m],
                                       vt[(m + 1) * 68 + c] * ci[m + 1]);
        *(__half2*)(g_Vph + ((size_t)b * CC + c) * LL + m0 + 2 * jp) = hv;
    }
}

// ---------------------------------------------------------------------------
// Kernel 4 (pass2): fused S GEMM -> exp -> Y GEMM (unchanged from R14/R15).
// ---------------------------------------------------------------------------
#define P2_Q0 0
#define P2_Q1 16384
#define P2_V0 32768
#define P2_V1 49152
#define P2_TOT 65536

__global__ __launch_bounds__(128, 3) void pass2(float* __restrict__ out) {
    extern __shared__ char smraw[];
    const uint32_t sb = smem_u32(smraw);

    const int tid = threadIdx.x;
    const int lane = tid & 31;
    const int wid = tid >> 5;
    const int g = lane >> 2, q = lane & 3;
    const int b = blockIdx.y;
    const int l0 = blockIdx.x * TL;
    const int r0 = wid * 32;

    uint32_t Ka0[4][4], Ka1[4][4];
#pragma unroll
    for (int ks = 0; ks < 4; ks++) {
        uint2 lo = *(const uint2*)(g_Kh + ((size_t)b * LL + l0 + r0 + g) * DK + 16 * ks + 4 * q);
        uint2 hi = *(const uint2*)(g_Kh + ((size_t)b * LL + l0 + r0 + g + 8) * DK + 16 * ks + 4 * q);
        Ka0[ks][0] = lo.x; Ka0[ks][2] = lo.y;
        Ka0[ks][1] = hi.x; Ka0[ks][3] = hi.y;
        uint2 lo1 = *(const uint2*)(g_Kh + ((size_t)b * LL + l0 + r0 + 16 + g) * DK + 16 * ks + 4 * q);
        uint2 hi1 = *(const uint2*)(g_Kh + ((size_t)b * LL + l0 + r0 + 24 + g) * DK + 16 * ks + 4 * q);
        Ka1[ks][0] = lo1.x; Ka1[ks][2] = lo1.y;
        Ka1[ks][1] = hi1.x; Ka1[ks][3] = hi1.y;
    }

    float y0[8][4], y1[8][4];
#pragma unroll
    for (int n = 0; n < 8; n++)
#pragma unroll
        for (int e = 0; e < 4; e++) { y0[n][e] = 0.f; y1[n][e] = 0.f; }

#define P2_STAGE(qbase, vbase, m0_)                                                 \
    do {                                                                            \
        const __half* qsrc = g_Qh + ((size_t)b * LL + (m0_)) * DK;                  \
        for (int idx = tid; idx < 1024; idx += 128) {                               \
            int row = idx >> 3, c8 = idx & 7;                                       \
            uint32_t d = (qbase) + (uint32_t)(row * 128 +                           \
                          32 * (((c8 >> 1) ^ (row & 3))) + 16 * (c8 & 1));          \
            cpa16(d, qsrc + (size_t)row * DK + 8 * c8);                             \
        }                                                                           \
        const __half* vsrc = g_Vph + (size_t)b * CC * LL + (m0_);                   \
        for (int idx = tid; idx < 1024; idx += 128) {                               \
            int row = idx >> 4, c8 = idx & 15;                                      \
            uint32_t d = (vbase) + (uint32_t)(row * 256 +                           \
                          32 * (((c8 >> 1) ^ (row & 3))) + 16 * (c8 & 1));          \
            cpa16(d, vsrc + (size_t)row * LL + 8 * c8);                             \
        }                                                                           \
    } while (0)

    P2_STAGE(sb + P2_Q0, sb + P2_V0, 0);
    CP_COMMIT();

    for (int mt = 0; mt < NMT; mt++) {
        CP_WAIT0();
        __syncthreads();
        if (mt < NMT - 1) {
            uint32_t qb = sb + (((mt + 1) & 1) ? P2_Q1 : P2_Q0);
            uint32_t vb = sb + (((mt + 1) & 1) ? P2_V1 : P2_V0);
            P2_STAGE(qb, vb, (mt + 1) * 128);
            CP_COMMIT();
        }
        const __half* Qc = (const __half*)(smraw + ((mt & 1) ? P2_Q1 : P2_Q0));
        const __half* Vc = (const __half*)(smraw + ((mt & 1) ? P2_V1 : P2_V0));

#pragma unroll
        for (int t = 0; t < 8; t++) {
            float a0A[4] = {0.f,0.f,0.f,0.f}, a1A[4] = {0.f,0.f,0.f,0.f};
            float a0B[4] = {0.f,0.f,0.f,0.f}, a1B[4] = {0.f,0.f,0.f,0.f};
#pragma unroll
            for (int ks = 0; ks < 4; ks++) {
                int co = 16 * (ks ^ (g & 3)) + 4 * q;
                uint2 q0 = *(const uint2*)&Qc[(16 * t + g) * 64 + co];
                uint2 q1 = *(const uint2*)&Qc[(16 * t + 8 + g) * 64 + co];
                mma16(a0A, Ka0[ks][0], Ka0[ks][1], Ka0[ks][2], Ka0[ks][3], q0.x, q0.y);
                mma16(a1A, Ka0[ks][0], Ka0[ks][1], Ka0[ks][2], Ka0[ks][3], q1.x, q1.y);
                mma16(a0B, Ka1[ks][0], Ka1[ks][1], Ka1[ks][2], Ka1[ks][3], q0.x, q0.y);
                mma16(a1B, Ka1[ks][0], Ka1[ks][1], Ka1[ks][2], Ka1[ks][3], q1.x, q1.y);
            }
            uint32_t pxA0 = ex2h2(packh2(a0A[0], a0A[1]));
            uint32_t pxA1 = ex2h2(packh2(a0A[2], a0A[3]));
            uint32_t pyA0 = ex2h2(packh2(a1A[0], a1A[1]));
            uint32_t pyA1 = ex2h2(packh2(a1A[2], a1A[3]));
            uint32_t pxB0 = ex2h2(packh2(a0B[0], a0B[1]));
            uint32_t pxB1 = ex2h2(packh2(a0B[2], a0B[3]));
            uint32_t pyB0 = ex2h2(packh2(a1B[0], a1B[1]));
            uint32_t pyB1 = ex2h2(packh2(a1B[2], a1B[3]));

#pragma unroll
            for (int n = 0; n < 8; n++) {
                uint2 bb = *(const uint2*)&Vc[(8 * n + g) * 128 + 16 * (t ^ (g & 3)) + 4 * q];
                mma16(y0[n], pxA0, pxA1, pyA0, pyA1, bb.x, bb.y);
                mma16(y1[n], pxB0, pxB1, pyB0, pyB1, bb.x, bb.y);
            }
        }
    }

    float* ob0 = out + ((size_t)b * LL + l0 + r0) * CC;
    float* ob1 = out + ((size_t)b * LL + l0 + r0 + 16) * CC;
#pragma unroll
    for (int n = 0; n < 8; n++) {
        *(float2*)&ob0[(size_t)g * CC + 8 * n + 2 * q]       = make_float2(y0[n][0], y0[n][1]);
        *(float2*)&ob0[(size_t)(g + 8) * CC + 8 * n + 2 * q] = make_float2(y0[n][2], y0[n][3]);
        *(float2*)&ob1[(size_t)g * CC + 8 * n + 2 * q]       = make_float2(y1[n][0], y1[n][1]);
        *(float2*)&ob1[(size_t)(g + 8) * CC + 8 * n + 2 * q] = make_float2(y1[n][2], y1[n][3]);
    }
}

// ---------------------------------------------------------------------------
extern "C" void kernel_launch(void* const* d_in, const int* in_sizes, int n_in,
                              void* d_out, int out_size) {
    const float* x  = (const float*)d_in[0];
    const float* Wk = (const float*)d_in[1];
    const float* bk = (const float*)d_in[2];
    const float* Wq = (const float*)d_in[3];
    const float* bq = (const float*)d_in[4];
    const float* Wv = (const float*)d_in[5];
    const float* bv = (const float*)d_in[6];
    const void*  sl = (const void*)d_in[7];
    float* out = (float*)d_out;

    const int kq_smem = KQ_TOT * (int)sizeof(float);
    const int p1_smem = P1_TOT;
    const int p2_smem = P2_TOT;

    static bool attr_set = false;
    if (!attr_set) {
        cudaFuncSetAttribute(kqv_mma, cudaFuncAttributeMaxDynamicSharedMemorySize, kq_smem);
        cudaFuncSetAttribute(pass1,   cudaFuncAttributeMaxDynamicSharedMemorySize, p1_smem);
        cudaFuncSetAttribute(pass2,   cudaFuncAttributeMaxDynamicSharedMemorySize, p2_smem);
        attr_set = true;
    }

    setup_kernel<<<32, 256>>>(Wk, bk, Wq, bq, Wv, bv);

    dim3 g1(NLT, BB);
    kqv_mma<<<g1, 256, kq_smem>>>(x, sl);

    dim3 g2(NLT, BB);
    pass1<<<g2, 128, p1_smem>>>();

    dim3 g3(LL / 64, BB);
    prep_kernel<<<g3, 256>>>();

    dim3 g4(NLT, BB);
    pass2<<<g4, 128, p2_smem>>>(out);
}